// round 11
// baseline (speedup 1.0000x reference)
#include <cuda_runtime.h>
#include <cuda_bf16.h>
#include <math.h>
#include <float.h>
#include <stdint.h>

#define MAXN 50000
#define MAXE 800000
#define DMAX 256

// ---------------- static device scratch ----------------
__device__ float g_q[(size_t)MAXN * DMAX];
__device__ float g_k[(size_t)MAXN * DMAX];
__device__ float g_v[(size_t)MAXN * DMAX];
__device__ float g_h1[(size_t)MAXN * DMAX];
__device__ float g_h2[(size_t)MAXN * DMAX];
__device__ int g_src[MAXE];
__device__ int g_dst[MAXE];
__device__ int g_ssrc[MAXE];
__device__ int g_deg[MAXN];
__device__ int g_off[MAXN + 1];
__device__ int g_cursor[MAXN];
__device__ int g_part[256];
__device__ int g_is64;
__device__ float g_psum[256];
__device__ unsigned g_pmax[256];

// pre-split bf16 operands (16B-aligned via uint4 backing)
__device__ uint4 g_ah4[(size_t)MAXN * 512 / 8];   // A hi
__device__ uint4 g_al4[(size_t)MAXN * 512 / 8];   // A lo
__device__ uint4 g_wh4[81920];                     // W hi
__device__ uint4 g_wl4[81920];                     // W lo
#define WOFF_L2 524288

__device__ __forceinline__ float* sel(int w) {
    switch (w) {
        case 0: return g_q;
        case 1: return g_k;
        case 2: return g_v;
        case 3: return g_h1;
        default: return g_h2;
    }
}

__device__ __forceinline__ unsigned fenc(float f) {
    unsigned u = __float_as_uint(f);
    return (u & 0x80000000u) ? ~u : (u | 0x80000000u);
}
__device__ __forceinline__ float fdec(unsigned u) {
    u = (u & 0x80000000u) ? (u ^ 0x80000000u) : ~u;
    return __uint_as_float(u);
}
#define ENC_NEG_INF 0x007FFFFFu

// ---------------- PTX helpers ----------------
__device__ __forceinline__ uint32_t smem_u32(const void* p) {
    uint32_t a;
    asm("{ .reg .u64 t; cvta.to.shared.u64 t, %1; cvt.u32.u64 %0, t; }" : "=r"(a) : "l"(p));
    return a;
}

__device__ __forceinline__ void ldm_x4(uint32_t& r0, uint32_t& r1, uint32_t& r2, uint32_t& r3,
                                       uint32_t addr) {
    asm volatile("ldmatrix.sync.aligned.m8n8.x4.shared.b16 {%0,%1,%2,%3}, [%4];"
        : "=r"(r0), "=r"(r1), "=r"(r2), "=r"(r3) : "r"(addr));
}

__device__ __forceinline__ void mma_bf16(float* c, const uint32_t* a, const uint32_t* b) {
    asm volatile("mma.sync.aligned.m16n8k16.row.col.f32.bf16.bf16.f32 "
        "{%0,%1,%2,%3}, {%4,%5,%6,%7}, {%8,%9}, {%0,%1,%2,%3};"
        : "+f"(c[0]), "+f"(c[1]), "+f"(c[2]), "+f"(c[3])
        : "r"(a[0]), "r"(a[1]), "r"(a[2]), "r"(a[3]), "r"(b[0]), "r"(b[1]));
}

__device__ __forceinline__ void cp16(uint32_t saddr, const void* gptr, int srcsize) {
    asm volatile("cp.async.ca.shared.global [%0], [%1], 16, %2;"
        :: "r"(saddr), "l"(gptr), "r"(srcsize) : "memory");
}
__device__ __forceinline__ void cp_commit() {
    asm volatile("cp.async.commit_group;" ::: "memory");
}
__device__ __forceinline__ void cp_wait0() {
    asm volatile("cp.async.wait_group 0;" ::: "memory");
}
__device__ __forceinline__ void cp_wait1() {
    asm volatile("cp.async.wait_group 1;" ::: "memory");
}

__device__ __forceinline__ uint32_t pack_bf(float a, float b) {
    __nv_bfloat162 t = __floats2bfloat162_rn(a, b);
    return *(uint32_t*)&t;
}
__device__ __forceinline__ float bf_hi_val(float v, float& lo) {
    __nv_bfloat16 h = __float2bfloat16_rn(v);
    float hf = __bfloat162float(h);
    lo = v - hf;
    return hf;
}

// ---------------- graph preprocessing ----------------
__global__ void detect_kernel(const unsigned* __restrict__ ei, int E) {
    if (threadIdx.x == 0 && blockIdx.x == 0) {
        int n = E < 64 ? E : 64;
        int is64 = 1;
        for (int i = 0; i < n; i++) {
            if (ei[2 * i + 1] != 0u) { is64 = 0; break; }
        }
        g_is64 = is64;
    }
}

__global__ void zero_deg_kernel(int Nn) {
    int i = blockIdx.x * blockDim.x + threadIdx.x;
    if (i < Nn) g_deg[i] = 0;
}

__global__ void convert_kernel(const void* __restrict__ ei, int E) {
    int i = blockIdx.x * blockDim.x + threadIdx.x;
    if (i >= E) return;
    int s, t;
    if (g_is64) {
        const long long* p = (const long long*)ei;
        s = (int)p[i];
        t = (int)p[E + i];
    } else {
        const int* p = (const int*)ei;
        s = p[i];
        t = p[E + i];
    }
    g_src[i] = s;
    g_dst[i] = t;
    atomicAdd(&g_deg[t], 1);
}

__global__ void part_sum_kernel(int Nn) {
    __shared__ int red[256];
    int t = threadIdx.x;
    int i = blockIdx.x * 256 + t;
    red[t] = (i < Nn) ? g_deg[i] : 0;
    __syncthreads();
    for (int o = 128; o; o >>= 1) {
        if (t < o) red[t] += red[t + o];
        __syncthreads();
    }
    if (t == 0) g_part[blockIdx.x] = red[0];
}

__global__ void part_scan_kernel(int nb, int Nn) {
    __shared__ int s[256];
    int t = threadIdx.x;
    s[t] = (t < nb) ? g_part[t] : 0;
    __syncthreads();
    for (int o = 1; o < 256; o <<= 1) {
        int u = (t >= o) ? s[t - o] : 0;
        __syncthreads();
        s[t] += u;
        __syncthreads();
    }
    g_part[t] = (t > 0) ? s[t - 1] : 0;
    if (t == 255) g_off[Nn] = s[255];
}

__global__ void off_kernel(int Nn) {
    __shared__ int s[256];
    int t = threadIdx.x;
    int i = blockIdx.x * 256 + t;
    int v = (i < Nn) ? g_deg[i] : 0;
    s[t] = v;
    __syncthreads();
    for (int o = 1; o < 256; o <<= 1) {
        int u = (t >= o) ? s[t - o] : 0;
        __syncthreads();
        s[t] += u;
        __syncthreads();
    }
    if (i < Nn) {
        int excl = s[t] - v + g_part[blockIdx.x];
        g_off[i] = excl;
        g_cursor[i] = excl;
    }
}

__global__ void permute_kernel(int E) {
    int i = blockIdx.x * blockDim.x + threadIdx.x;
    if (i >= E) return;
    int t = g_dst[i];
    int pos = atomicAdd(&g_cursor[t], 1);
    g_ssrc[pos] = g_src[i];
}

// ---------------- operand pre-splitting ----------------
__global__ void split_a_kernel(const float* __restrict__ Aext, int a_sel,
                               int total4, int sanitize) {
    int i = blockIdx.x * blockDim.x + threadIdx.x;
    if (i >= total4) return;
    const float* A = (a_sel >= 0) ? sel(a_sel) : Aext;
    float4 v = ((const float4*)A)[i];
    if (sanitize) {
        if (v.x != v.x) v.x = 0.f;
        if (v.y != v.y) v.y = 0.f;
        if (v.z != v.z) v.z = 0.f;
        if (v.w != v.w) v.w = 0.f;
    }
    float lx, ly, lz, lw;
    float hx = bf_hi_val(v.x, lx);
    float hy = bf_hi_val(v.y, ly);
    float hz = bf_hi_val(v.z, lz);
    float hw = bf_hi_val(v.w, lw);
    ((uint2*)g_ah4)[i] = make_uint2(pack_bf(hx, hy), pack_bf(hz, hw));
    ((uint2*)g_al4)[i] = make_uint2(pack_bf(lx, ly), pack_bf(lz, lw));
}

__global__ void split_w_kernel(const float* __restrict__ W0, const float* __restrict__ W1,
                               const float* __restrict__ W2, const float* __restrict__ W3,
                               int K, int Nt, int base) {
    int i = blockIdx.x * blockDim.x + threadIdx.x;
    if (i >= K * Nt) return;
    int w = blockIdx.y;
    const float* W = (w == 0) ? W0 : (w == 1) ? W1 : (w == 2) ? W2 : W3;
    int k = i / Nt, n = i - k * Nt;
    float v = W[i];
    float lo;
    float hi = bf_hi_val(v, lo);
    size_t o = (size_t)base + (size_t)w * K * Nt + (size_t)n * K + k;
    ((__nv_bfloat16*)g_wh4)[o] = __float2bfloat16_rn(hi);
    ((__nv_bfloat16*)g_wl4)[o] = __float2bfloat16_rn(lo);
}

// ================= bf16 mma.sync GEMM, cp.async pipeline, occ 2 =================
#define OFF_AH 0
#define OFF_AL 10240
#define OFF_BH 20480
#define OFF_BL 30720
#define BUF_SZ 40960
#define GEMM_SMEM (2 * BUF_SZ)

__global__ __launch_bounds__(256, 2)
void gemm_mma_kernel(int wbase,
                     const float* __restrict__ b0, const float* __restrict__ b1,
                     const float* __restrict__ b2, const float* __restrict__ b3,
                     int c0, int c1, int c2, int c3,
                     int M, int K, int Nt) {
    extern __shared__ char smem[];
    const uint32_t sbase = smem_u32(smem);

    const int tid = threadIdx.x;
    const int wid = tid >> 5;
    const int lid = tid & 31;
    const int wm = wid & 1;
    const int wn = wid >> 1;
    const int rowBase = blockIdx.y * 128;

    const int cbPerW = Nt >> 7;
    const int wsel = blockIdx.x / cbPerW;
    const int colBase = (blockIdx.x - wsel * cbPerW) * 128;

    const __nv_bfloat16* Ah = (const __nv_bfloat16*)g_ah4;
    const __nv_bfloat16* Al = (const __nv_bfloat16*)g_al4;
    const __nv_bfloat16* Wh = (const __nv_bfloat16*)g_wh4 + (size_t)wbase + (size_t)wsel * K * Nt;
    const __nv_bfloat16* Wl = (const __nv_bfloat16*)g_wl4 + (size_t)wbase + (size_t)wsel * K * Nt;

    const float* bias;
    int csel;
    switch (wsel) {
        case 0: bias = b0; csel = c0; break;
        case 1: bias = b1; csel = c1; break;
        case 2: bias = b2; csel = c2; break;
        default: bias = b3; csel = c3; break;
    }
    float* C = sel(csel);

    float acc[4][4][4];
#pragma unroll
    for (int i = 0; i < 4; i++)
#pragma unroll
        for (int j = 0; j < 4; j++)
#pragma unroll
            for (int q = 0; q < 4; q++) acc[i][j][q] = 0.f;

    const int l_row = tid >> 2;
    const int l_kq = tid & 3;
    const int nChunks = K >> 5;

    const int grow0 = rowBase + l_row;
    const int grow1 = rowBase + l_row + 64;
    const int a_ok0 = (grow0 < M) ? 16 : 0;
    const int a_ok1 = (grow1 < M) ? 16 : 0;
    const int n0 = colBase + l_row;
    const int n1 = colBase + l_row + 64;
    const uint32_t soff0 = (uint32_t)(l_row * 80 + l_kq * 16);
    const uint32_t soff1 = soff0 + 64 * 80;

    auto issue = [&](int c, int b) {
        const int k0 = c << 5;
        uint32_t bb = sbase + b * BUF_SZ;
        cp16(bb + OFF_AH + soff0, Ah + (size_t)grow0 * K + k0 + l_kq * 8, a_ok0);
        cp16(bb + OFF_AL + soff0, Al + (size_t)grow0 * K + k0 + l_kq * 8, a_ok0);
        cp16(bb + OFF_AH + soff1, Ah + (size_t)grow1 * K + k0 + l_kq * 8, a_ok1);
        cp16(bb + OFF_AL + soff1, Al + (size_t)grow1 * K + k0 + l_kq * 8, a_ok1);
        cp16(bb + OFF_BH + soff0, Wh + (size_t)n0 * K + k0 + l_kq * 8, 16);
        cp16(bb + OFF_BL + soff0, Wl + (size_t)n0 * K + k0 + l_kq * 8, 16);
        cp16(bb + OFF_BH + soff1, Wh + (size_t)n1 * K + k0 + l_kq * 8, 16);
        cp16(bb + OFF_BL + soff1, Wl + (size_t)n1 * K + k0 + l_kq * 8, 16);
        cp_commit();
    };

    issue(0, 0);

    int buf = 0;
    for (int c = 0; c < nChunks; c++) {
        if (c + 1 < nChunks) {
            issue(c + 1, buf ^ 1);
            cp_wait1();
        } else {
            cp_wait0();
        }
        __syncthreads();

        uint32_t bb = sbase + buf * BUF_SZ;
        const int lr = lid & 15;
        const int lc = lid >> 4;
        uint32_t AHB = bb + OFF_AH, ALB = bb + OFF_AL;
        uint32_t BHB = bb + OFF_BH, BLB = bb + OFF_BL;
#pragma unroll
        for (int ks = 0; ks < 2; ks++) {
            uint32_t koff = (uint32_t)(ks * 32 + lc * 16);
            uint32_t ah[4][4], al[4][4], bh[4][2], bl[4][2];
#pragma unroll
            for (int i = 0; i < 4; i++) {
                uint32_t ro = (uint32_t)((wm * 64 + i * 16 + lr) * 80) + koff;
                ldm_x4(ah[i][0], ah[i][1], ah[i][2], ah[i][3], AHB + ro);
                ldm_x4(al[i][0], al[i][1], al[i][2], al[i][3], ALB + ro);
            }
#pragma unroll
            for (int j2 = 0; j2 < 2; j2++) {
                uint32_t ro = (uint32_t)((wn * 32 + j2 * 16 + lr) * 80) + koff;
                uint32_t r0, r1, r2, r3;
                ldm_x4(r0, r1, r2, r3, BHB + ro);
                bh[j2 * 2 + 0][0] = r0; bh[j2 * 2 + 0][1] = r2;
                bh[j2 * 2 + 1][0] = r1; bh[j2 * 2 + 1][1] = r3;
                ldm_x4(r0, r1, r2, r3, BLB + ro);
                bl[j2 * 2 + 0][0] = r0; bl[j2 * 2 + 0][1] = r2;
                bl[j2 * 2 + 1][0] = r1; bl[j2 * 2 + 1][1] = r3;
            }
#pragma unroll
            for (int i = 0; i < 4; i++)
#pragma unroll
                for (int j = 0; j < 4; j++) {
                    mma_bf16(acc[i][j], ah[i], bh[j]);
                    mma_bf16(acc[i][j], ah[i], bl[j]);
                    mma_bf16(acc[i][j], al[i], bh[j]);
                }
        }
        __syncthreads();
        buf ^= 1;
    }

    const int lr4 = lid >> 2;
    const int lc2 = (lid & 3) * 2;
#pragma unroll
    for (int j = 0; j < 4; j++) {
        int gc = colBase + wn * 32 + j * 8 + lc2;
        float bi0 = bias[gc], bi1 = bias[gc + 1];
#pragma unroll
        for (int i = 0; i < 4; i++) {
            int gr0 = rowBase + wm * 64 + i * 16 + lr4;
            int gr1 = gr0 + 8;
            if (gr0 < M) {
                float2 o = make_float2(acc[i][j][0] + bi0, acc[i][j][1] + bi1);
                *(float2*)(C + (size_t)gr0 * Nt + gc) = o;
            }
            if (gr1 < M) {
                float2 o = make_float2(acc[i][j][2] + bi0, acc[i][j][3] + bi1);
                *(float2*)(C + (size_t)gr1 * Nt + gc) = o;
            }
        }
    }
}

// ================= fused per-node edge kernel: ONLINE softmax, single pass =================
// One warp per dst node; k and v rows gathered together (MLP 8), no smem, no spill.
__global__ __launch_bounds__(256)
void edge_online_kernel(int Nn, int d, int h_sel, float inv_sqrt_d, int do_split) {
    int gw = (blockIdx.x * blockDim.x + threadIdx.x) >> 5;
    int lane = threadIdx.x & 31;
    if (gw >= Nn) return;
    int beg = g_off[gw];
    int deg = g_off[gw + 1] - beg;

    const int nv = d >> 7;   // 1 (d=128) or 2 (d=256)
    float4 a0 = make_float4(0.f, 0.f, 0.f, 0.f);
    float4 a1 = make_float4(0.f, 0.f, 0.f, 0.f);

    if (deg > 0) {
        const float* qr = g_q + (size_t)gw * d;
        float4 q0 = *(const float4*)(qr + lane * 4);
        float4 q1 = make_float4(0.f, 0.f, 0.f, 0.f);
        if (nv > 1) q1 = *(const float4*)(qr + 128 + lane * 4);

        float mx = -FLT_MAX;
        float den = 0.f;
        int j = 0;
        for (; j + 1 < deg; j += 2) {
            int s0 = g_ssrc[beg + j];
            int s1 = g_ssrc[beg + j + 1];
            const float* k0p = g_k + (size_t)s0 * d;
            const float* k1p = g_k + (size_t)s1 * d;
            const float* v0p = g_v + (size_t)s0 * d;
            const float* v1p = g_v + (size_t)s1 * d;
            // issue all gathers up front (MLP 8 at d=256)
            float4 kb0 = *(const float4*)(k0p + lane * 4);
            float4 kc0 = *(const float4*)(k1p + lane * 4);
            float4 vb0 = *(const float4*)(v0p + lane * 4);
            float4 vc0 = *(const float4*)(v1p + lane * 4);
            float4 kb1, kc1, vb1, vc1;
            if (nv > 1) {
                kb1 = *(const float4*)(k0p + 128 + lane * 4);
                kc1 = *(const float4*)(k1p + 128 + lane * 4);
                vb1 = *(const float4*)(v0p + 128 + lane * 4);
                vc1 = *(const float4*)(v1p + 128 + lane * 4);
            }
            float sa = q0.x * kb0.x + q0.y * kb0.y + q0.z * kb0.z + q0.w * kb0.w;
            float sb = q0.x * kc0.x + q0.y * kc0.y + q0.z * kc0.z + q0.w * kc0.w;
            if (nv > 1) {
                sa += q1.x * kb1.x + q1.y * kb1.y + q1.z * kb1.z + q1.w * kb1.w;
                sb += q1.x * kc1.x + q1.y * kc1.y + q1.z * kc1.z + q1.w * kc1.w;
            }
#pragma unroll
            for (int o = 16; o; o >>= 1) {
                sa += __shfl_xor_sync(0xFFFFFFFFu, sa, o);
                sb += __shfl_xor_sync(0xFFFFFFFFu, sb, o);
            }
            sa *= inv_sqrt_d;
            sb *= inv_sqrt_d;
            float mn = fmaxf(mx, fmaxf(sa, sb));
            float corr = __expf(mx - mn);      // 0 on first iter (mx = -FLT_MAX)
            float pa = __expf(sa - mn);
            float pb = __expf(sb - mn);
            den = den * corr + pa + pb;
            a0.x = a0.x * corr + pa * vb0.x + pb * vc0.x;
            a0.y = a0.y * corr + pa * vb0.y + pb * vc0.y;
            a0.z = a0.z * corr + pa * vb0.z + pb * vc0.z;
            a0.w = a0.w * corr + pa * vb0.w + pb * vc0.w;
            if (nv > 1) {
                a1.x = a1.x * corr + pa * vb1.x + pb * vc1.x;
                a1.y = a1.y * corr + pa * vb1.y + pb * vc1.y;
                a1.z = a1.z * corr + pa * vb1.z + pb * vc1.z;
                a1.w = a1.w * corr + pa * vb1.w + pb * vc1.w;
            }
            mx = mn;
        }
        if (j < deg) {
            int s = g_ssrc[beg + j];
            const float* kp = g_k + (size_t)s * d;
            const float* vp = g_v + (size_t)s * d;
            float4 kb0 = *(const float4*)(kp + lane * 4);
            float4 vb0 = *(const float4*)(vp + lane * 4);
            float4 kb1, vb1;
            if (nv > 1) {
                kb1 = *(const float4*)(kp + 128 + lane * 4);
                vb1 = *(const float4*)(vp + 128 + lane * 4);
            }
            float sa = q0.x * kb0.x + q0.y * kb0.y + q0.z * kb0.z + q0.w * kb0.w;
            if (nv > 1)
                sa += q1.x * kb1.x + q1.y * kb1.y + q1.z * kb1.z + q1.w * kb1.w;
#pragma unroll
            for (int o = 16; o; o >>= 1) sa += __shfl_xor_sync(0xFFFFFFFFu, sa, o);
            sa *= inv_sqrt_d;
            float mn = fmaxf(mx, sa);
            float corr = __expf(mx - mn);
            float pa = __expf(sa - mn);
            den = den * corr + pa;
            a0.x = a0.x * corr + pa * vb0.x;
            a0.y = a0.y * corr + pa * vb0.y;
            a0.z = a0.z * corr + pa * vb0.z;
            a0.w = a0.w * corr + pa * vb0.w;
            if (nv > 1) {
                a1.x = a1.x * corr + pa * vb1.x;
                a1.y = a1.y * corr + pa * vb1.y;
                a1.z = a1.z * corr + pa * vb1.z;
                a1.w = a1.w * corr + pa * vb1.w;
            }
        }
        float rden = 1.f / den;
        a0.x *= rden; a0.y *= rden; a0.z *= rden; a0.w *= rden;
        if (nv > 1) { a1.x *= rden; a1.y *= rden; a1.z *= rden; a1.w *= rden; }
    }

    float* hr = sel(h_sel) + (size_t)gw * d;
    float4 h0 = *(float4*)(hr + lane * 4);
    h0.x += a0.x; h0.y += a0.y; h0.z += a0.z; h0.w += a0.w;
    *(float4*)(hr + lane * 4) = h0;
    float4 h1 = make_float4(0.f, 0.f, 0.f, 0.f);
    if (nv > 1) {
        h1 = *(float4*)(hr + 128 + lane * 4);
        h1.x += a1.x; h1.y += a1.y; h1.z += a1.z; h1.w += a1.w;
        *(float4*)(hr + 128 + lane * 4) = h1;
    }

    // fused bf16 hi/lo split of the final h row (feeds layer-2 GEMM)
    if (do_split) {
        __nv_bfloat16* AhP = (__nv_bfloat16*)g_ah4;
        __nv_bfloat16* AlP = (__nv_bfloat16*)g_al4;
        float lx, ly, lz, lw;
        float hx = bf_hi_val(h0.x, lx);
        float hy = bf_hi_val(h0.y, ly);
        float hz = bf_hi_val(h0.z, lz);
        float hw = bf_hi_val(h0.w, lw);
        *(uint2*)(AhP + (size_t)gw * d + lane * 4) = make_uint2(pack_bf(hx, hy), pack_bf(hz, hw));
        *(uint2*)(AlP + (size_t)gw * d + lane * 4) = make_uint2(pack_bf(lx, ly), pack_bf(lz, lw));
        if (nv > 1) {
            float hx1 = bf_hi_val(h1.x, lx);
            float hy1 = bf_hi_val(h1.y, ly);
            float hz1 = bf_hi_val(h1.z, lz);
            float hw1 = bf_hi_val(h1.w, lw);
            *(uint2*)(AhP + (size_t)gw * d + 128 + lane * 4) = make_uint2(pack_bf(hx1, hy1), pack_bf(hz1, hw1));
            *(uint2*)(AlP + (size_t)gw * d + 128 + lane * 4) = make_uint2(pack_bf(lx, ly), pack_bf(lz, lw));
        }
    }
}

// ---------------- pooling ----------------
__global__ void pool_init_kernel() {
    int c = threadIdx.x;
    if (c < 256) {
        g_psum[c] = 0.f;
        g_pmax[c] = ENC_NEG_INF;
    }
}

__global__ void pool_kernel(int M, int d) {
    int c = threadIdx.x;
    const float* h = g_h2;
    float sum = 0.f, mx = -FLT_MAX;
    for (int r = blockIdx.x; r < M; r += gridDim.x) {
        float v = h[(size_t)r * d + c];
        sum += v;
        mx = fmaxf(mx, v);
    }
    atomicAdd(&g_psum[c], sum);
    atomicMax(&g_pmax[c], fenc(mx));
}

__global__ void pool_final_kernel(float* __restrict__ out, int M, int d) {
    int c = threadIdx.x;
    if (c < d) {
        out[c] = g_psum[c] / (float)M;
        out[d + c] = fdec(g_pmax[c]);
    }
}

// ---------------- launch ----------------
extern "C" void kernel_launch(void* const* d_in, const int* in_sizes, int n_in,
                              void* d_out, int out_size) {
    const float* x   = (const float*)d_in[0];
    const void*  ei  = d_in[1];
    const float* Wq1 = (const float*)d_in[3];
    const float* bq1 = (const float*)d_in[4];
    const float* Wk1 = (const float*)d_in[5];
    const float* bk1 = (const float*)d_in[6];
    const float* Wv1 = (const float*)d_in[7];
    const float* bv1 = (const float*)d_in[8];
    const float* Ws1 = (const float*)d_in[9];
    const float* bs1 = (const float*)d_in[10];
    const float* Wq2 = (const float*)d_in[11];
    const float* bq2 = (const float*)d_in[12];
    const float* Wk2 = (const float*)d_in[13];
    const float* bk2 = (const float*)d_in[14];
    const float* Wv2 = (const float*)d_in[15];
    const float* bv2 = (const float*)d_in[16];
    const float* Ws2 = (const float*)d_in[17];
    const float* bs2 = (const float*)d_in[18];
    float* out = (float*)d_out;

    const int D_IN = 512, D_HID = 256, D_OUT = 128;
    int Nn = in_sizes[0] / D_IN;
    int E  = in_sizes[2];

    static int smem_set = 0;
    if (!smem_set) {
        cudaFuncSetAttribute(gemm_mma_kernel,
                             cudaFuncAttributeMaxDynamicSharedMemorySize, GEMM_SMEM);
        smem_set = 1;
    }

    // ---- graph preprocessing: CSR by dst ----
    int nb = (Nn + 255) / 256;
    detect_kernel<<<1, 32>>>((const unsigned*)ei, E);
    zero_deg_kernel<<<nb, 256>>>(Nn);
    convert_kernel<<<(E + 255) / 256, 256>>>(ei, E);
    part_sum_kernel<<<nb, 256>>>(Nn);
    part_scan_kernel<<<1, 256>>>(nb, Nn);
    off_kernel<<<nb, 256>>>(Nn);
    permute_kernel<<<(E + 255) / 256, 256>>>(E);

    // ---- weight pre-split (both layers, once) ----
    {
        dim3 g1((D_IN * D_HID + 255) / 256, 4);
        split_w_kernel<<<g1, 256>>>(Wq1, Wk1, Wv1, Ws1, D_IN, D_HID, 0);
        dim3 g2((D_HID * D_OUT + 255) / 256, 4);
        split_w_kernel<<<g2, 256>>>(Wq2, Wk2, Wv2, Ws2, D_HID, D_OUT, WOFF_L2);
    }

    int nTiles = (Nn + 127) / 128;
    int edgeBlks = (Nn * 32 + 255) / 256;

    // ===== layer 1 =====
    {
        int t4 = Nn * D_IN / 4;
        split_a_kernel<<<(t4 + 255) / 256, 256>>>(x, -1, t4, 1);
        dim3 g(8, nTiles);
        gemm_mma_kernel<<<g, 256, GEMM_SMEM>>>(
            0, bq1, bk1, bv1, bs1, 0, 1, 2, 3, Nn, D_IN, D_HID);
    }
    edge_online_kernel<<<edgeBlks, 256>>>(Nn, D_HID, 3,
        (float)(1.0 / sqrt((double)D_HID)), 1);

    // ===== layer 2 (A split produced by layer-1 edge kernel) =====
    {
        dim3 g(4, nTiles);
        gemm_mma_kernel<<<g, 256, GEMM_SMEM>>>(
            WOFF_L2, bq2, bk2, bv2, bs2, 0, 1, 2, 4, Nn, D_HID, D_OUT);
    }
    edge_online_kernel<<<edgeBlks, 256>>>(Nn, D_OUT, 4,
        (float)(1.0 / sqrt((double)D_OUT)), 0);

    // ===== pooling =====
    pool_init_kernel<<<1, 256>>>();
    pool_kernel<<<256, D_OUT>>>(Nn, D_OUT);
    pool_final_kernel<<<1, 256>>>(out, Nn, D_OUT);
}

// round 12
// speedup vs baseline: 1.3641x; 1.3641x over previous
#include <cuda_runtime.h>
#include <cuda_bf16.h>
#include <math.h>
#include <float.h>
#include <stdint.h>

#define MAXN 50000
#define MAXE 800000
#define DMAX 256
#define DEG_CAP 64

// ---------------- static device scratch ----------------
__device__ float g_q[(size_t)MAXN * DMAX];
__device__ float g_k[(size_t)MAXN * DMAX];
__device__ float g_v[(size_t)MAXN * DMAX];
__device__ float g_h1[(size_t)MAXN * DMAX];
__device__ float g_h2[(size_t)MAXN * DMAX];
__device__ float g_score[MAXE];
__device__ int g_src[MAXE];
__device__ int g_dst[MAXE];
__device__ int g_ssrc[MAXE];
__device__ int g_deg[MAXN];
__device__ int g_off[MAXN + 1];
__device__ int g_cursor[MAXN];
__device__ int g_part[256];
__device__ int g_is64;
__device__ float g_psum[256];
__device__ unsigned g_pmax[256];

// pre-split bf16 operands (16B-aligned via uint4 backing)
__device__ uint4 g_ah4[(size_t)MAXN * 512 / 8];   // A hi
__device__ uint4 g_al4[(size_t)MAXN * 512 / 8];   // A lo
__device__ uint4 g_wh4[81920];                     // W hi
__device__ uint4 g_wl4[81920];                     // W lo
#define WOFF_L2 524288

__device__ __forceinline__ float* sel(int w) {
    switch (w) {
        case 0: return g_q;
        case 1: return g_k;
        case 2: return g_v;
        case 3: return g_h1;
        default: return g_h2;
    }
}

__device__ __forceinline__ unsigned fenc(float f) {
    unsigned u = __float_as_uint(f);
    return (u & 0x80000000u) ? ~u : (u | 0x80000000u);
}
__device__ __forceinline__ float fdec(unsigned u) {
    u = (u & 0x80000000u) ? (u ^ 0x80000000u) : ~u;
    return __uint_as_float(u);
}
#define ENC_NEG_INF 0x007FFFFFu

// ---------------- PTX helpers ----------------
__device__ __forceinline__ uint32_t smem_u32(const void* p) {
    uint32_t a;
    asm("{ .reg .u64 t; cvta.to.shared.u64 t, %1; cvt.u32.u64 %0, t; }" : "=r"(a) : "l"(p));
    return a;
}

__device__ __forceinline__ void ldm_x4(uint32_t& r0, uint32_t& r1, uint32_t& r2, uint32_t& r3,
                                       uint32_t addr) {
    asm volatile("ldmatrix.sync.aligned.m8n8.x4.shared.b16 {%0,%1,%2,%3}, [%4];"
        : "=r"(r0), "=r"(r1), "=r"(r2), "=r"(r3) : "r"(addr));
}

__device__ __forceinline__ void mma_bf16(float* c, const uint32_t* a, const uint32_t* b) {
    asm volatile("mma.sync.aligned.m16n8k16.row.col.f32.bf16.bf16.f32 "
        "{%0,%1,%2,%3}, {%4,%5,%6,%7}, {%8,%9}, {%0,%1,%2,%3};"
        : "+f"(c[0]), "+f"(c[1]), "+f"(c[2]), "+f"(c[3])
        : "r"(a[0]), "r"(a[1]), "r"(a[2]), "r"(a[3]), "r"(b[0]), "r"(b[1]));
}

__device__ __forceinline__ void cp16(uint32_t saddr, const void* gptr, int srcsize) {
    asm volatile("cp.async.ca.shared.global [%0], [%1], 16, %2;"
        :: "r"(saddr), "l"(gptr), "r"(srcsize) : "memory");
}
__device__ __forceinline__ void cp_commit() {
    asm volatile("cp.async.commit_group;" ::: "memory");
}
__device__ __forceinline__ void cp_wait0() {
    asm volatile("cp.async.wait_group 0;" ::: "memory");
}
__device__ __forceinline__ void cp_wait1() {
    asm volatile("cp.async.wait_group 1;" ::: "memory");
}

__device__ __forceinline__ uint32_t pack_bf(float a, float b) {
    __nv_bfloat162 t = __floats2bfloat162_rn(a, b);
    return *(uint32_t*)&t;
}
__device__ __forceinline__ float bf_hi_val(float v, float& lo) {
    __nv_bfloat16 h = __float2bfloat16_rn(v);
    float hf = __bfloat162float(h);
    lo = v - hf;
    return hf;
}

// ---------------- graph preprocessing ----------------
__global__ void detect_kernel(const unsigned* __restrict__ ei, int E) {
    if (threadIdx.x == 0 && blockIdx.x == 0) {
        int n = E < 64 ? E : 64;
        int is64 = 1;
        for (int i = 0; i < n; i++) {
            if (ei[2 * i + 1] != 0u) { is64 = 0; break; }
        }
        g_is64 = is64;
    }
}

__global__ void zero_deg_kernel(int Nn) {
    int i = blockIdx.x * blockDim.x + threadIdx.x;
    if (i < Nn) g_deg[i] = 0;
}

__global__ void convert_kernel(const void* __restrict__ ei, int E) {
    int i = blockIdx.x * blockDim.x + threadIdx.x;
    if (i >= E) return;
    int s, t;
    if (g_is64) {
        const long long* p = (const long long*)ei;
        s = (int)p[i];
        t = (int)p[E + i];
    } else {
        const int* p = (const int*)ei;
        s = p[i];
        t = p[E + i];
    }
    g_src[i] = s;
    g_dst[i] = t;
    atomicAdd(&g_deg[t], 1);
}

__global__ void part_sum_kernel(int Nn) {
    __shared__ int red[256];
    int t = threadIdx.x;
    int i = blockIdx.x * 256 + t;
    red[t] = (i < Nn) ? g_deg[i] : 0;
    __syncthreads();
    for (int o = 128; o; o >>= 1) {
        if (t < o) red[t] += red[t + o];
        __syncthreads();
    }
    if (t == 0) g_part[blockIdx.x] = red[0];
}

__global__ void part_scan_kernel(int nb, int Nn) {
    __shared__ int s[256];
    int t = threadIdx.x;
    s[t] = (t < nb) ? g_part[t] : 0;
    __syncthreads();
    for (int o = 1; o < 256; o <<= 1) {
        int u = (t >= o) ? s[t - o] : 0;
        __syncthreads();
        s[t] += u;
        __syncthreads();
    }
    g_part[t] = (t > 0) ? s[t - 1] : 0;
    if (t == 255) g_off[Nn] = s[255];
}

__global__ void off_kernel(int Nn) {
    __shared__ int s[256];
    int t = threadIdx.x;
    int i = blockIdx.x * 256 + t;
    int v = (i < Nn) ? g_deg[i] : 0;
    s[t] = v;
    __syncthreads();
    for (int o = 1; o < 256; o <<= 1) {
        int u = (t >= o) ? s[t - o] : 0;
        __syncthreads();
        s[t] += u;
        __syncthreads();
    }
    if (i < Nn) {
        int excl = s[t] - v + g_part[blockIdx.x];
        g_off[i] = excl;
        g_cursor[i] = excl;
    }
}

__global__ void permute_kernel(int E) {
    int i = blockIdx.x * blockDim.x + threadIdx.x;
    if (i >= E) return;
    int t = g_dst[i];
    int pos = atomicAdd(&g_cursor[t], 1);
    g_ssrc[pos] = g_src[i];
}

// ---------------- operand pre-splitting ----------------
__global__ void split_a_kernel(const float* __restrict__ Aext, int a_sel,
                               int total4, int sanitize) {
    int i = blockIdx.x * blockDim.x + threadIdx.x;
    if (i >= total4) return;
    const float* A = (a_sel >= 0) ? sel(a_sel) : Aext;
    float4 v = ((const float4*)A)[i];
    if (sanitize) {
        if (v.x != v.x) v.x = 0.f;
        if (v.y != v.y) v.y = 0.f;
        if (v.z != v.z) v.z = 0.f;
        if (v.w != v.w) v.w = 0.f;
    }
    float lx, ly, lz, lw;
    float hx = bf_hi_val(v.x, lx);
    float hy = bf_hi_val(v.y, ly);
    float hz = bf_hi_val(v.z, lz);
    float hw = bf_hi_val(v.w, lw);
    ((uint2*)g_ah4)[i] = make_uint2(pack_bf(hx, hy), pack_bf(hz, hw));
    ((uint2*)g_al4)[i] = make_uint2(pack_bf(lx, ly), pack_bf(lz, lw));
}

__global__ void split_w_kernel(const float* __restrict__ W0, const float* __restrict__ W1,
                               const float* __restrict__ W2, const float* __restrict__ W3,
                               int K, int Nt, int base) {
    int i = blockIdx.x * blockDim.x + threadIdx.x;
    if (i >= K * Nt) return;
    int w = blockIdx.y;
    const float* W = (w == 0) ? W0 : (w == 1) ? W1 : (w == 2) ? W2 : W3;
    int k = i / Nt, n = i - k * Nt;
    float v = W[i];
    float lo;
    float hi = bf_hi_val(v, lo);
    size_t o = (size_t)base + (size_t)w * K * Nt + (size_t)n * K + k;
    ((__nv_bfloat16*)g_wh4)[o] = __float2bfloat16_rn(hi);
    ((__nv_bfloat16*)g_wl4)[o] = __float2bfloat16_rn(lo);
}

// ================= bf16 mma.sync GEMM, cp.async pipeline, occ 2 =================
#define OFF_AH 0
#define OFF_AL 10240
#define OFF_BH 20480
#define OFF_BL 30720
#define BUF_SZ 40960
#define GEMM_SMEM (2 * BUF_SZ)

__global__ __launch_bounds__(256, 2)
void gemm_mma_kernel(int wbase,
                     const float* __restrict__ b0, const float* __restrict__ b1,
                     const float* __restrict__ b2, const float* __restrict__ b3,
                     int c0, int c1, int c2, int c3,
                     int M, int K, int Nt) {
    extern __shared__ char smem[];
    const uint32_t sbase = smem_u32(smem);

    const int tid = threadIdx.x;
    const int wid = tid >> 5;
    const int lid = tid & 31;
    const int wm = wid & 1;
    const int wn = wid >> 1;
    const int rowBase = blockIdx.y * 128;

    const int cbPerW = Nt >> 7;
    const int wsel = blockIdx.x / cbPerW;
    const int colBase = (blockIdx.x - wsel * cbPerW) * 128;

    const __nv_bfloat16* Ah = (const __nv_bfloat16*)g_ah4;
    const __nv_bfloat16* Al = (const __nv_bfloat16*)g_al4;
    const __nv_bfloat16* Wh = (const __nv_bfloat16*)g_wh4 + (size_t)wbase + (size_t)wsel * K * Nt;
    const __nv_bfloat16* Wl = (const __nv_bfloat16*)g_wl4 + (size_t)wbase + (size_t)wsel * K * Nt;

    const float* bias;
    int csel;
    switch (wsel) {
        case 0: bias = b0; csel = c0; break;
        case 1: bias = b1; csel = c1; break;
        case 2: bias = b2; csel = c2; break;
        default: bias = b3; csel = c3; break;
    }
    float* C = sel(csel);

    float acc[4][4][4];
#pragma unroll
    for (int i = 0; i < 4; i++)
#pragma unroll
        for (int j = 0; j < 4; j++)
#pragma unroll
            for (int q = 0; q < 4; q++) acc[i][j][q] = 0.f;

    const int l_row = tid >> 2;
    const int l_kq = tid & 3;
    const int nChunks = K >> 5;

    const int grow0 = rowBase + l_row;
    const int grow1 = rowBase + l_row + 64;
    const int a_ok0 = (grow0 < M) ? 16 : 0;
    const int a_ok1 = (grow1 < M) ? 16 : 0;
    const int n0 = colBase + l_row;
    const int n1 = colBase + l_row + 64;
    const uint32_t soff0 = (uint32_t)(l_row * 80 + l_kq * 16);
    const uint32_t soff1 = soff0 + 64 * 80;

    auto issue = [&](int c, int b) {
        const int k0 = c << 5;
        uint32_t bb = sbase + b * BUF_SZ;
        cp16(bb + OFF_AH + soff0, Ah + (size_t)grow0 * K + k0 + l_kq * 8, a_ok0);
        cp16(bb + OFF_AL + soff0, Al + (size_t)grow0 * K + k0 + l_kq * 8, a_ok0);
        cp16(bb + OFF_AH + soff1, Ah + (size_t)grow1 * K + k0 + l_kq * 8, a_ok1);
        cp16(bb + OFF_AL + soff1, Al + (size_t)grow1 * K + k0 + l_kq * 8, a_ok1);
        cp16(bb + OFF_BH + soff0, Wh + (size_t)n0 * K + k0 + l_kq * 8, 16);
        cp16(bb + OFF_BL + soff0, Wl + (size_t)n0 * K + k0 + l_kq * 8, 16);
        cp16(bb + OFF_BH + soff1, Wh + (size_t)n1 * K + k0 + l_kq * 8, 16);
        cp16(bb + OFF_BL + soff1, Wl + (size_t)n1 * K + k0 + l_kq * 8, 16);
        cp_commit();
    };

    issue(0, 0);

    int buf = 0;
    for (int c = 0; c < nChunks; c++) {
        if (c + 1 < nChunks) {
            issue(c + 1, buf ^ 1);
            cp_wait1();
        } else {
            cp_wait0();
        }
        __syncthreads();

        uint32_t bb = sbase + buf * BUF_SZ;
        const int lr = lid & 15;
        const int lc = lid >> 4;
        uint32_t AHB = bb + OFF_AH, ALB = bb + OFF_AL;
        uint32_t BHB = bb + OFF_BH, BLB = bb + OFF_BL;
#pragma unroll
        for (int ks = 0; ks < 2; ks++) {
            uint32_t koff = (uint32_t)(ks * 32 + lc * 16);
            uint32_t ah[4][4], al[4][4], bh[4][2], bl[4][2];
#pragma unroll
            for (int i = 0; i < 4; i++) {
                uint32_t ro = (uint32_t)((wm * 64 + i * 16 + lr) * 80) + koff;
                ldm_x4(ah[i][0], ah[i][1], ah[i][2], ah[i][3], AHB + ro);
                ldm_x4(al[i][0], al[i][1], al[i][2], al[i][3], ALB + ro);
            }
#pragma unroll
            for (int j2 = 0; j2 < 2; j2++) {
                uint32_t ro = (uint32_t)((wn * 32 + j2 * 16 + lr) * 80) + koff;
                uint32_t r0, r1, r2, r3;
                ldm_x4(r0, r1, r2, r3, BHB + ro);
                bh[j2 * 2 + 0][0] = r0; bh[j2 * 2 + 0][1] = r2;
                bh[j2 * 2 + 1][0] = r1; bh[j2 * 2 + 1][1] = r3;
                ldm_x4(r0, r1, r2, r3, BLB + ro);
                bl[j2 * 2 + 0][0] = r0; bl[j2 * 2 + 0][1] = r2;
                bl[j2 * 2 + 1][0] = r1; bl[j2 * 2 + 1][1] = r3;
            }
#pragma unroll
            for (int i = 0; i < 4; i++)
#pragma unroll
                for (int j = 0; j < 4; j++) {
                    mma_bf16(acc[i][j], ah[i], bh[j]);
                    mma_bf16(acc[i][j], ah[i], bl[j]);
                    mma_bf16(acc[i][j], al[i], bh[j]);
                }
        }
        __syncthreads();
        buf ^= 1;
    }

    const int lr4 = lid >> 2;
    const int lc2 = (lid & 3) * 2;
#pragma unroll
    for (int j = 0; j < 4; j++) {
        int gc = colBase + wn * 32 + j * 8 + lc2;
        float bi0 = bias[gc], bi1 = bias[gc + 1];
#pragma unroll
        for (int i = 0; i < 4; i++) {
            int gr0 = rowBase + wm * 64 + i * 16 + lr4;
            int gr1 = gr0 + 8;
            if (gr0 < M) {
                float2 o = make_float2(acc[i][j][0] + bi0, acc[i][j][1] + bi1);
                *(float2*)(C + (size_t)gr0 * Nt + gc) = o;
            }
            if (gr1 < M) {
                float2 o = make_float2(acc[i][j][2] + bi0, acc[i][j][3] + bi1);
                *(float2*)(C + (size_t)gr1 * Nt + gc) = o;
            }
        }
    }
}

// ================= fused per-node edge kernel (two-pass, R10 structure) =================
// Pass 1: 2-edge pipelined score+max.  Pass 3: 4-edge unrolled aggregate.
__global__ __launch_bounds__(256)
void edge_fused_kernel(int Nn, int d, int h_sel, float inv_sqrt_d, int do_split) {
    __shared__ float sc[8][DEG_CAP];
    int gw = (blockIdx.x * blockDim.x + threadIdx.x) >> 5;
    int lane = threadIdx.x & 31;
    int wIn = threadIdx.x >> 5;
    if (gw >= Nn) return;
    int beg = g_off[gw];
    int deg = g_off[gw + 1] - beg;

    const int nv = d >> 7;
    float4 a0 = make_float4(0.f, 0.f, 0.f, 0.f);
    float4 a1 = make_float4(0.f, 0.f, 0.f, 0.f);

    if (deg > 0) {
        const float* qr = g_q + (size_t)gw * d;
        float4 q0 = *(const float4*)(qr + lane * 4);
        float4 q1 = make_float4(0.f, 0.f, 0.f, 0.f);
        if (nv > 1) q1 = *(const float4*)(qr + 128 + lane * 4);

        // ---- pass 1: scores + max (2-edge pipelined) ----
        float mx = -FLT_MAX;
        int j = 0;
        for (; j + 1 < deg; j += 2) {
            int s0 = g_ssrc[beg + j];
            int s1 = g_ssrc[beg + j + 1];
            const float* k0p = g_k + (size_t)s0 * d;
            const float* k1p = g_k + (size_t)s1 * d;
            float4 b0 = *(const float4*)(k0p + lane * 4);
            float4 c0 = *(const float4*)(k1p + lane * 4);
            float sa = q0.x * b0.x + q0.y * b0.y + q0.z * b0.z + q0.w * b0.w;
            float sb = q0.x * c0.x + q0.y * c0.y + q0.z * c0.z + q0.w * c0.w;
            if (nv > 1) {
                float4 b1 = *(const float4*)(k0p + 128 + lane * 4);
                float4 c1 = *(const float4*)(k1p + 128 + lane * 4);
                sa += q1.x * b1.x + q1.y * b1.y + q1.z * b1.z + q1.w * b1.w;
                sb += q1.x * c1.x + q1.y * c1.y + q1.z * c1.z + q1.w * c1.w;
            }
#pragma unroll
            for (int o = 16; o; o >>= 1) {
                sa += __shfl_xor_sync(0xFFFFFFFFu, sa, o);
                sb += __shfl_xor_sync(0xFFFFFFFFu, sb, o);
            }
            sa *= inv_sqrt_d;
            sb *= inv_sqrt_d;
            mx = fmaxf(mx, fmaxf(sa, sb));
            if (lane == 0) {
                if (j < DEG_CAP) sc[wIn][j] = sa; else g_score[beg + j] = sa;
                if (j + 1 < DEG_CAP) sc[wIn][j + 1] = sb; else g_score[beg + j + 1] = sb;
            }
        }
        if (j < deg) {
            int s = g_ssrc[beg + j];
            const float* kr = g_k + (size_t)s * d;
            float4 b0 = *(const float4*)(kr + lane * 4);
            float sum = q0.x * b0.x + q0.y * b0.y + q0.z * b0.z + q0.w * b0.w;
            if (nv > 1) {
                float4 b1 = *(const float4*)(kr + 128 + lane * 4);
                sum += q1.x * b1.x + q1.y * b1.y + q1.z * b1.z + q1.w * b1.w;
            }
#pragma unroll
            for (int o = 16; o; o >>= 1) sum += __shfl_xor_sync(0xFFFFFFFFu, sum, o);
            sum *= inv_sqrt_d;
            mx = fmaxf(mx, sum);
            if (lane == 0) {
                if (j < DEG_CAP) sc[wIn][j] = sum; else g_score[beg + j] = sum;
            }
        }
        __syncwarp();

        // ---- pass 2: exp + denom ----
        float den = 0.f;
        for (int jj = lane; jj < deg; jj += 32) {
            float v = (jj < DEG_CAP) ? sc[wIn][jj] : g_score[beg + jj];
            float e = __expf(v - mx);
            if (jj < DEG_CAP) sc[wIn][jj] = e;
            else g_score[beg + jj] = e;
            den += e;
        }
#pragma unroll
        for (int o = 16; o; o >>= 1) den += __shfl_xor_sync(0xFFFFFFFFu, den, o);
        float rden = 1.f / den;
        __syncwarp();

        // ---- pass 3: weighted aggregate (4-edge unrolled) ----
        j = 0;
        for (; j + 3 < deg; j += 4) {
            int s0 = g_ssrc[beg + j];
            int s1 = g_ssrc[beg + j + 1];
            int s2 = g_ssrc[beg + j + 2];
            int s3 = g_ssrc[beg + j + 3];
            float e0 = (j < DEG_CAP) ? sc[wIn][j] : g_score[beg + j];
            float e1 = (j + 1 < DEG_CAP) ? sc[wIn][j + 1] : g_score[beg + j + 1];
            float e2 = (j + 2 < DEG_CAP) ? sc[wIn][j + 2] : g_score[beg + j + 2];
            float e3 = (j + 3 < DEG_CAP) ? sc[wIn][j + 3] : g_score[beg + j + 3];
            float al0 = e0 * rden, al1 = e1 * rden, al2 = e2 * rden, al3 = e3 * rden;
            const float* v0p = g_v + (size_t)s0 * d;
            const float* v1p = g_v + (size_t)s1 * d;
            const float* v2p = g_v + (size_t)s2 * d;
            const float* v3p = g_v + (size_t)s3 * d;
            float4 b0 = *(const float4*)(v0p + lane * 4);
            float4 c0 = *(const float4*)(v1p + lane * 4);
            float4 d0 = *(const float4*)(v2p + lane * 4);
            float4 f0 = *(const float4*)(v3p + lane * 4);
            a0.x += al0 * b0.x + al1 * c0.x + al2 * d0.x + al3 * f0.x;
            a0.y += al0 * b0.y + al1 * c0.y + al2 * d0.y + al3 * f0.y;
            a0.z += al0 * b0.z + al1 * c0.z + al2 * d0.z + al3 * f0.z;
            a0.w += al0 * b0.w + al1 * c0.w + al2 * d0.w + al3 * f0.w;
            if (nv > 1) {
                float4 b1 = *(const float4*)(v0p + 128 + lane * 4);
                float4 c1 = *(const float4*)(v1p + 128 + lane * 4);
                float4 d1 = *(const float4*)(v2p + 128 + lane * 4);
                float4 f1 = *(const float4*)(v3p + 128 + lane * 4);
                a1.x += al0 * b1.x + al1 * c1.x + al2 * d1.x + al3 * f1.x;
                a1.y += al0 * b1.y + al1 * c1.y + al2 * d1.y + al3 * f1.y;
                a1.z += al0 * b1.z + al1 * c1.z + al2 * d1.z + al3 * f1.z;
                a1.w += al0 * b1.w + al1 * c1.w + al2 * d1.w + al3 * f1.w;
            }
        }
        for (; j < deg; j++) {
            int s = g_ssrc[beg + j];
            float e = (j < DEG_CAP) ? sc[wIn][j] : g_score[beg + j];
            float alpha = e * rden;
            const float* vr = g_v + (size_t)s * d;
            float4 b0 = *(const float4*)(vr + lane * 4);
            a0.x += alpha * b0.x; a0.y += alpha * b0.y;
            a0.z += alpha * b0.z; a0.w += alpha * b0.w;
            if (nv > 1) {
                float4 b1 = *(const float4*)(vr + 128 + lane * 4);
                a1.x += alpha * b1.x; a1.y += alpha * b1.y;
                a1.z += alpha * b1.z; a1.w += alpha * b1.w;
            }
        }
    }

    float* hr = sel(h_sel) + (size_t)gw * d;
    float4 h0 = *(float4*)(hr + lane * 4);
    h0.x += a0.x; h0.y += a0.y; h0.z += a0.z; h0.w += a0.w;
    *(float4*)(hr + lane * 4) = h0;
    float4 h1 = make_float4(0.f, 0.f, 0.f, 0.f);
    if (nv > 1) {
        h1 = *(float4*)(hr + 128 + lane * 4);
        h1.x += a1.x; h1.y += a1.y; h1.z += a1.z; h1.w += a1.w;
        *(float4*)(hr + 128 + lane * 4) = h1;
    }

    // fused bf16 hi/lo split of the final h row (feeds layer-2 GEMM)
    if (do_split) {
        __nv_bfloat16* AhP = (__nv_bfloat16*)g_ah4;
        __nv_bfloat16* AlP = (__nv_bfloat16*)g_al4;
        float lx, ly, lz, lw;
        float hx = bf_hi_val(h0.x, lx);
        float hy = bf_hi_val(h0.y, ly);
        float hz = bf_hi_val(h0.z, lz);
        float hw = bf_hi_val(h0.w, lw);
        *(uint2*)(AhP + (size_t)gw * d + lane * 4) = make_uint2(pack_bf(hx, hy), pack_bf(hz, hw));
        *(uint2*)(AlP + (size_t)gw * d + lane * 4) = make_uint2(pack_bf(lx, ly), pack_bf(lz, lw));
        if (nv > 1) {
            float hx1 = bf_hi_val(h1.x, lx);
            float hy1 = bf_hi_val(h1.y, ly);
            float hz1 = bf_hi_val(h1.z, lz);
            float hw1 = bf_hi_val(h1.w, lw);
            *(uint2*)(AhP + (size_t)gw * d + 128 + lane * 4) = make_uint2(pack_bf(hx1, hy1), pack_bf(hz1, hw1));
            *(uint2*)(AlP + (size_t)gw * d + 128 + lane * 4) = make_uint2(pack_bf(lx, ly), pack_bf(lz, lw));
        }
    }
}

// ---------------- pooling ----------------
__global__ void pool_init_kernel() {
    int c = threadIdx.x;
    if (c < 256) {
        g_psum[c] = 0.f;
        g_pmax[c] = ENC_NEG_INF;
    }
}

__global__ void pool_kernel(int M, int d) {
    int c = threadIdx.x;
    const float* h = g_h2;
    float sum = 0.f, mx = -FLT_MAX;
    for (int r = blockIdx.x; r < M; r += gridDim.x) {
        float v = h[(size_t)r * d + c];
        sum += v;
        mx = fmaxf(mx, v);
    }
    atomicAdd(&g_psum[c], sum);
    atomicMax(&g_pmax[c], fenc(mx));
}

__global__ void pool_final_kernel(float* __restrict__ out, int M, int d) {
    int c = threadIdx.x;
    if (c < d) {
        out[c] = g_psum[c] / (float)M;
        out[d + c] = fdec(g_pmax[c]);
    }
}

// ---------------- launch ----------------
extern "C" void kernel_launch(void* const* d_in, const int* in_sizes, int n_in,
                              void* d_out, int out_size) {
    const float* x   = (const float*)d_in[0];
    const void*  ei  = d_in[1];
    const float* Wq1 = (const float*)d_in[3];
    const float* bq1 = (const float*)d_in[4];
    const float* Wk1 = (const float*)d_in[5];
    const float* bk1 = (const float*)d_in[6];
    const float* Wv1 = (const float*)d_in[7];
    const float* bv1 = (const float*)d_in[8];
    const float* Ws1 = (const float*)d_in[9];
    const float* bs1 = (const float*)d_in[10];
    const float* Wq2 = (const float*)d_in[11];
    const float* bq2 = (const float*)d_in[12];
    const float* Wk2 = (const float*)d_in[13];
    const float* bk2 = (const float*)d_in[14];
    const float* Wv2 = (const float*)d_in[15];
    const float* bv2 = (const float*)d_in[16];
    const float* Ws2 = (const float*)d_in[17];
    const float* bs2 = (const float*)d_in[18];
    float* out = (float*)d_out;

    const int D_IN = 512, D_HID = 256, D_OUT = 128;
    int Nn = in_sizes[0] / D_IN;
    int E  = in_sizes[2];

    static int smem_set = 0;
    if (!smem_set) {
        cudaFuncSetAttribute(gemm_mma_kernel,
                             cudaFuncAttributeMaxDynamicSharedMemorySize, GEMM_SMEM);
        smem_set = 1;
    }

    // ---- graph preprocessing: CSR by dst ----
    int nb = (Nn + 255) / 256;
    detect_kernel<<<1, 32>>>((const unsigned*)ei, E);
    zero_deg_kernel<<<nb, 256>>>(Nn);
    convert_kernel<<<(E + 255) / 256, 256>>>(ei, E);
    part_sum_kernel<<<nb, 256>>>(Nn);
    part_scan_kernel<<<1, 256>>>(nb, Nn);
    off_kernel<<<nb, 256>>>(Nn);
    permute_kernel<<<(E + 255) / 256, 256>>>(E);

    // ---- weight pre-split (both layers, once) ----
    {
        dim3 g1((D_IN * D_HID + 255) / 256, 4);
        split_w_kernel<<<g1, 256>>>(Wq1, Wk1, Wv1, Ws1, D_IN, D_HID, 0);
        dim3 g2((D_HID * D_OUT + 255) / 256, 4);
        split_w_kernel<<<g2, 256>>>(Wq2, Wk2, Wv2, Ws2, D_HID, D_OUT, WOFF_L2);
    }

    int nTiles = (Nn + 127) / 128;
    int edgeBlks = (Nn * 32 + 255) / 256;

    // ===== layer 1 =====
    {
        int t4 = Nn * D_IN / 4;
        split_a_kernel<<<(t4 + 255) / 256, 256>>>(x, -1, t4, 1);
        dim3 g(8, nTiles);
        gemm_mma_kernel<<<g, 256, GEMM_SMEM>>>(
            0, bq1, bk1, bv1, bs1, 0, 1, 2, 3, Nn, D_IN, D_HID);
    }
    edge_fused_kernel<<<edgeBlks, 256>>>(Nn, D_HID, 3,
        (float)(1.0 / sqrt((double)D_HID)), 1);

    // ===== layer 2 (A split produced by layer-1 edge kernel) =====
    {
        dim3 g(4, nTiles);
        gemm_mma_kernel<<<g, 256, GEMM_SMEM>>>(
            WOFF_L2, bq2, bk2, bv2, bs2, 0, 1, 2, 4, Nn, D_HID, D_OUT);
    }
    edge_fused_kernel<<<edgeBlks, 256>>>(Nn, D_OUT, 4,
        (float)(1.0 / sqrt((double)D_OUT)), 0);

    // ===== pooling =====
    pool_init_kernel<<<1, 256>>>();
    pool_kernel<<<256, D_OUT>>>(Nn, D_OUT);
    pool_final_kernel<<<1, 256>>>(out, Nn, D_OUT);
}

// round 13
// speedup vs baseline: 1.3680x; 1.0029x over previous
#include <cuda_runtime.h>
#include <cuda_bf16.h>
#include <math.h>
#include <float.h>
#include <stdint.h>

#define MAXN 50000
#define MAXE 800000
#define DMAX 256
#define DEG_CAP 64

// ---------------- static device scratch ----------------
__device__ float g_q[(size_t)MAXN * DMAX];
__device__ float g_k[(size_t)MAXN * DMAX];
__device__ float g_v[(size_t)MAXN * DMAX];
__device__ float g_h1[(size_t)MAXN * DMAX];
__device__ float g_h2[(size_t)MAXN * DMAX];
__device__ float g_score[MAXE];
__device__ int g_src[MAXE];
__device__ int g_dst[MAXE];
__device__ int g_ssrc[MAXE];
__device__ int g_deg[MAXN];
__device__ int g_off[MAXN + 1];
__device__ int g_cursor[MAXN];
__device__ int g_part[256];
__device__ int g_is64;
__device__ float g_psum[256];
__device__ unsigned g_pmax[256];

// pre-split bf16 operands
__device__ uint4 g_ah4[(size_t)MAXN * 512 / 8];
__device__ uint4 g_al4[(size_t)MAXN * 512 / 8];
__device__ uint4 g_wh4[81920];
__device__ uint4 g_wl4[81920];
#define WOFF_L2 524288

__device__ __forceinline__ float* sel(int w) {
    switch (w) {
        case 0: return g_q;
        case 1: return g_k;
        case 2: return g_v;
        case 3: return g_h1;
        default: return g_h2;
    }
}

__device__ __forceinline__ unsigned fenc(float f) {
    unsigned u = __float_as_uint(f);
    return (u & 0x80000000u) ? ~u : (u | 0x80000000u);
}
__device__ __forceinline__ float fdec(unsigned u) {
    u = (u & 0x80000000u) ? (u ^ 0x80000000u) : ~u;
    return __uint_as_float(u);
}
#define ENC_NEG_INF 0x007FFFFFu

// ---------------- PTX helpers ----------------
__device__ __forceinline__ uint32_t smem_u32(const void* p) {
    uint32_t a;
    asm("{ .reg .u64 t; cvta.to.shared.u64 t, %1; cvt.u32.u64 %0, t; }" : "=r"(a) : "l"(p));
    return a;
}

__device__ __forceinline__ void ldm_x4(uint32_t& r0, uint32_t& r1, uint32_t& r2, uint32_t& r3,
                                       uint32_t addr) {
    asm volatile("ldmatrix.sync.aligned.m8n8.x4.shared.b16 {%0,%1,%2,%3}, [%4];"
        : "=r"(r0), "=r"(r1), "=r"(r2), "=r"(r3) : "r"(addr));
}

__device__ __forceinline__ void mma_bf16(float* c, const uint32_t* a, const uint32_t* b) {
    asm volatile("mma.sync.aligned.m16n8k16.row.col.f32.bf16.bf16.f32 "
        "{%0,%1,%2,%3}, {%4,%5,%6,%7}, {%8,%9}, {%0,%1,%2,%3};"
        : "+f"(c[0]), "+f"(c[1]), "+f"(c[2]), "+f"(c[3])
        : "r"(a[0]), "r"(a[1]), "r"(a[2]), "r"(a[3]), "r"(b[0]), "r"(b[1]));
}

__device__ __forceinline__ void cp16(uint32_t saddr, const void* gptr, int srcsize) {
    asm volatile("cp.async.ca.shared.global [%0], [%1], 16, %2;"
        :: "r"(saddr), "l"(gptr), "r"(srcsize) : "memory");
}
__device__ __forceinline__ void cp_commit() {
    asm volatile("cp.async.commit_group;" ::: "memory");
}
__device__ __forceinline__ void cp_wait0() {
    asm volatile("cp.async.wait_group 0;" ::: "memory");
}
__device__ __forceinline__ void cp_wait1() {
    asm volatile("cp.async.wait_group 1;" ::: "memory");
}

__device__ __forceinline__ uint32_t pack_bf(float a, float b) {
    __nv_bfloat162 t = __floats2bfloat162_rn(a, b);
    return *(uint32_t*)&t;
}
__device__ __forceinline__ float bf_hi_val(float v, float& lo) {
    __nv_bfloat16 h = __float2bfloat16_rn(v);
    float hf = __bfloat162float(h);
    lo = v - hf;
    return hf;
}

// ---------------- preprocessing stage 1: detect + zero degrees ----------------
__global__ void detect_zero_kernel(const unsigned* __restrict__ ei, int E, int Nn) {
    int i = blockIdx.x * blockDim.x + threadIdx.x;
    if (i < Nn) g_deg[i] = 0;
    if (i == 0) {
        int n = E < 64 ? E : 64;
        int is64 = 1;
        for (int j = 0; j < n; j++) {
            if (ei[2 * j + 1] != 0u) { is64 = 0; break; }
        }
        g_is64 = is64;
    }
}

// ---------------- preprocessing stage 2: fused convert + split_a + split_w ----------------
// block ranges: [0,b1) convert, [b1,b2) split_a L1, [b2,b3) split_w L1, [b3,b4) split_w L2
__global__ void fused_prep_kernel(
    const void* __restrict__ ei, int E,
    const float* __restrict__ x, int t4,
    const float* __restrict__ Wq1, const float* __restrict__ Wk1,
    const float* __restrict__ Wv1, const float* __restrict__ Ws1,
    const float* __restrict__ Wq2, const float* __restrict__ Wk2,
    const float* __restrict__ Wv2, const float* __restrict__ Ws2,
    int b1, int b2, int b3, int b4) {
    int blk = blockIdx.x;
    int tid = threadIdx.x;

    if (blk < b1) {
        // convert + degree histogram
        int i = blk * 256 + tid;
        if (i >= E) return;
        int s, t;
        if (g_is64) {
            const long long* p = (const long long*)ei;
            s = (int)p[i];
            t = (int)p[E + i];
        } else {
            const int* p = (const int*)ei;
            s = p[i];
            t = p[E + i];
        }
        g_src[i] = s;
        g_dst[i] = t;
        atomicAdd(&g_deg[t], 1);
    } else if (blk < b2) {
        // split_a layer-1 (sanitize NaN)
        int i = (blk - b1) * 256 + tid;
        if (i >= t4) return;
        float4 v = ((const float4*)x)[i];
        if (v.x != v.x) v.x = 0.f;
        if (v.y != v.y) v.y = 0.f;
        if (v.z != v.z) v.z = 0.f;
        if (v.w != v.w) v.w = 0.f;
        float lx, ly, lz, lw;
        float hx = bf_hi_val(v.x, lx);
        float hy = bf_hi_val(v.y, ly);
        float hz = bf_hi_val(v.z, lz);
        float hw = bf_hi_val(v.w, lw);
        ((uint2*)g_ah4)[i] = make_uint2(pack_bf(hx, hy), pack_bf(hz, hw));
        ((uint2*)g_al4)[i] = make_uint2(pack_bf(lx, ly), pack_bf(lz, lw));
    } else if (blk < b3) {
        // split_w layer-1: K=512, Nt=256, per-weight elems 131072
        int j = (blk - b2) * 256 + tid;
        int w = j >> 17;               // /131072
        int i = j & 131071;
        const float* W = (w == 0) ? Wq1 : (w == 1) ? Wk1 : (w == 2) ? Wv1 : Ws1;
        int k = i >> 8, n = i & 255;   // Nt=256
        float v = W[i];
        float lo;
        float hi = bf_hi_val(v, lo);
        size_t o = (size_t)w * 131072 + (size_t)n * 512 + k;
        ((__nv_bfloat16*)g_wh4)[o] = __float2bfloat16_rn(hi);
        ((__nv_bfloat16*)g_wl4)[o] = __float2bfloat16_rn(lo);
    } else if (blk < b4) {
        // split_w layer-2: K=256, Nt=128, per-weight elems 32768
        int j = (blk - b3) * 256 + tid;
        int w = j >> 15;               // /32768
        int i = j & 32767;
        const float* W = (w == 0) ? Wq2 : (w == 1) ? Wk2 : (w == 2) ? Wv2 : Ws2;
        int k = i >> 7, n = i & 127;   // Nt=128
        float v = W[i];
        float lo;
        float hi = bf_hi_val(v, lo);
        size_t o = (size_t)WOFF_L2 + (size_t)w * 32768 + (size_t)n * 256 + k;
        ((__nv_bfloat16*)g_wh4)[o] = __float2bfloat16_rn(hi);
        ((__nv_bfloat16*)g_wl4)[o] = __float2bfloat16_rn(lo);
    }
}

// ---------------- scan + permute ----------------
__global__ void part_sum_kernel(int Nn) {
    __shared__ int red[256];
    int t = threadIdx.x;
    int i = blockIdx.x * 256 + t;
    red[t] = (i < Nn) ? g_deg[i] : 0;
    __syncthreads();
    for (int o = 128; o; o >>= 1) {
        if (t < o) red[t] += red[t + o];
        __syncthreads();
    }
    if (t == 0) g_part[blockIdx.x] = red[0];
}

__global__ void part_scan_kernel(int nb, int Nn) {
    __shared__ int s[256];
    int t = threadIdx.x;
    s[t] = (t < nb) ? g_part[t] : 0;
    __syncthreads();
    for (int o = 1; o < 256; o <<= 1) {
        int u = (t >= o) ? s[t - o] : 0;
        __syncthreads();
        s[t] += u;
        __syncthreads();
    }
    g_part[t] = (t > 0) ? s[t - 1] : 0;
    if (t == 255) g_off[Nn] = s[255];
}

__global__ void off_kernel(int Nn) {
    __shared__ int s[256];
    int t = threadIdx.x;
    int i = blockIdx.x * 256 + t;
    int v = (i < Nn) ? g_deg[i] : 0;
    s[t] = v;
    __syncthreads();
    for (int o = 1; o < 256; o <<= 1) {
        int u = (t >= o) ? s[t - o] : 0;
        __syncthreads();
        s[t] += u;
        __syncthreads();
    }
    if (i < Nn) {
        int excl = s[t] - v + g_part[blockIdx.x];
        g_off[i] = excl;
        g_cursor[i] = excl;
    }
}

__global__ void permute_kernel(int E) {
    int i = blockIdx.x * blockDim.x + threadIdx.x;
    if (i >= E) return;
    int t = g_dst[i];
    int pos = atomicAdd(&g_cursor[t], 1);
    g_ssrc[pos] = g_src[i];
}

// ================= bf16 mma.sync GEMM, cp.async pipeline, occ 2 =================
#define OFF_AH 0
#define OFF_AL 10240
#define OFF_BH 20480
#define OFF_BL 30720
#define BUF_SZ 40960
#define GEMM_SMEM (2 * BUF_SZ)

__global__ __launch_bounds__(256, 2)
void gemm_mma_kernel(int wbase,
                     const float* __restrict__ b0, const float* __restrict__ b1,
                     const float* __restrict__ b2, const float* __restrict__ b3,
                     int c0, int c1, int c2, int c3,
                     int M, int K, int Nt) {
    extern __shared__ char smem[];
    const uint32_t sbase = smem_u32(smem);

    const int tid = threadIdx.x;
    const int wid = tid >> 5;
    const int lid = tid & 31;
    const int wm = wid & 1;
    const int wn = wid >> 1;
    const int rowBase = blockIdx.y * 128;

    const int cbPerW = Nt >> 7;
    const int wsel = blockIdx.x / cbPerW;
    const int colBase = (blockIdx.x - wsel * cbPerW) * 128;

    const __nv_bfloat16* Ah = (const __nv_bfloat16*)g_ah4;
    const __nv_bfloat16* Al = (const __nv_bfloat16*)g_al4;
    const __nv_bfloat16* Wh = (const __nv_bfloat16*)g_wh4 + (size_t)wbase + (size_t)wsel * K * Nt;
    const __nv_bfloat16* Wl = (const __nv_bfloat16*)g_wl4 + (size_t)wbase + (size_t)wsel * K * Nt;

    const float* bias;
    int csel;
    switch (wsel) {
        case 0: bias = b0; csel = c0; break;
        case 1: bias = b1; csel = c1; break;
        case 2: bias = b2; csel = c2; break;
        default: bias = b3; csel = c3; break;
    }
    float* C = sel(csel);

    float acc[4][4][4];
#pragma unroll
    for (int i = 0; i < 4; i++)
#pragma unroll
        for (int j = 0; j < 4; j++)
#pragma unroll
            for (int q = 0; q < 4; q++) acc[i][j][q] = 0.f;

    const int l_row = tid >> 2;
    const int l_kq = tid & 3;
    const int nChunks = K >> 5;

    const int grow0 = rowBase + l_row;
    const int grow1 = rowBase + l_row + 64;
    const int a_ok0 = (grow0 < M) ? 16 : 0;
    const int a_ok1 = (grow1 < M) ? 16 : 0;
    const int n0 = colBase + l_row;
    const int n1 = colBase + l_row + 64;
    const uint32_t soff0 = (uint32_t)(l_row * 80 + l_kq * 16);
    const uint32_t soff1 = soff0 + 64 * 80;

    auto issue = [&](int c, int b) {
        const int k0 = c << 5;
        uint32_t bb = sbase + b * BUF_SZ;
        cp16(bb + OFF_AH + soff0, Ah + (size_t)grow0 * K + k0 + l_kq * 8, a_ok0);
        cp16(bb + OFF_AL + soff0, Al + (size_t)grow0 * K + k0 + l_kq * 8, a_ok0);
        cp16(bb + OFF_AH + soff1, Ah + (size_t)grow1 * K + k0 + l_kq * 8, a_ok1);
        cp16(bb + OFF_AL + soff1, Al + (size_t)grow1 * K + k0 + l_kq * 8, a_ok1);
        cp16(bb + OFF_BH + soff0, Wh + (size_t)n0 * K + k0 + l_kq * 8, 16);
        cp16(bb + OFF_BL + soff0, Wl + (size_t)n0 * K + k0 + l_kq * 8, 16);
        cp16(bb + OFF_BH + soff1, Wh + (size_t)n1 * K + k0 + l_kq * 8, 16);
        cp16(bb + OFF_BL + soff1, Wl + (size_t)n1 * K + k0 + l_kq * 8, 16);
        cp_commit();
    };

    issue(0, 0);

    int buf = 0;
    for (int c = 0; c < nChunks; c++) {
        if (c + 1 < nChunks) {
            issue(c + 1, buf ^ 1);
            cp_wait1();
        } else {
            cp_wait0();
        }
        __syncthreads();

        uint32_t bb = sbase + buf * BUF_SZ;
        const int lr = lid & 15;
        const int lc = lid >> 4;
        uint32_t AHB = bb + OFF_AH, ALB = bb + OFF_AL;
        uint32_t BHB = bb + OFF_BH, BLB = bb + OFF_BL;
#pragma unroll
        for (int ks = 0; ks < 2; ks++) {
            uint32_t koff = (uint32_t)(ks * 32 + lc * 16);
            uint32_t ah[4][4], al[4][4], bh[4][2], bl[4][2];
#pragma unroll
            for (int i = 0; i < 4; i++) {
                uint32_t ro = (uint32_t)((wm * 64 + i * 16 + lr) * 80) + koff;
                ldm_x4(ah[i][0], ah[i][1], ah[i][2], ah[i][3], AHB + ro);
                ldm_x4(al[i][0], al[i][1], al[i][2], al[i][3], ALB + ro);
            }
#pragma unroll
            for (int j2 = 0; j2 < 2; j2++) {
                uint32_t ro = (uint32_t)((wn * 32 + j2 * 16 + lr) * 80) + koff;
                uint32_t r0, r1, r2, r3;
                ldm_x4(r0, r1, r2, r3, BHB + ro);
                bh[j2 * 2 + 0][0] = r0; bh[j2 * 2 + 0][1] = r2;
                bh[j2 * 2 + 1][0] = r1; bh[j2 * 2 + 1][1] = r3;
                ldm_x4(r0, r1, r2, r3, BLB + ro);
                bl[j2 * 2 + 0][0] = r0; bl[j2 * 2 + 0][1] = r2;
                bl[j2 * 2 + 1][0] = r1; bl[j2 * 2 + 1][1] = r3;
            }
#pragma unroll
            for (int i = 0; i < 4; i++)
#pragma unroll
                for (int j = 0; j < 4; j++) {
                    mma_bf16(acc[i][j], ah[i], bh[j]);
                    mma_bf16(acc[i][j], ah[i], bl[j]);
                    mma_bf16(acc[i][j], al[i], bh[j]);
                }
        }
        __syncthreads();
        buf ^= 1;
    }

    const int lr4 = lid >> 2;
    const int lc2 = (lid & 3) * 2;
#pragma unroll
    for (int j = 0; j < 4; j++) {
        int gc = colBase + wn * 32 + j * 8 + lc2;
        float bi0 = bias[gc], bi1 = bias[gc + 1];
#pragma unroll
        for (int i = 0; i < 4; i++) {
            int gr0 = rowBase + wm * 64 + i * 16 + lr4;
            int gr1 = gr0 + 8;
            if (gr0 < M) {
                float2 o = make_float2(acc[i][j][0] + bi0, acc[i][j][1] + bi1);
                *(float2*)(C + (size_t)gr0 * Nt + gc) = o;
            }
            if (gr1 < M) {
                float2 o = make_float2(acc[i][j][2] + bi0, acc[i][j][3] + bi1);
                *(float2*)(C + (size_t)gr1 * Nt + gc) = o;
            }
        }
    }
}

// ================= fused per-node edge kernel (two-pass; pass1 4-wide) =================
__global__ __launch_bounds__(256)
void edge_fused_kernel(int Nn, int d, int h_sel, float inv_sqrt_d, int do_split) {
    __shared__ float sc[8][DEG_CAP];
    int gw = (blockIdx.x * blockDim.x + threadIdx.x) >> 5;
    int lane = threadIdx.x & 31;
    int wIn = threadIdx.x >> 5;
    if (gw >= Nn) return;
    int beg = g_off[gw];
    int deg = g_off[gw + 1] - beg;

    const int nv = d >> 7;
    float4 a0 = make_float4(0.f, 0.f, 0.f, 0.f);
    float4 a1 = make_float4(0.f, 0.f, 0.f, 0.f);

    if (deg > 0) {
        const float* qr = g_q + (size_t)gw * d;
        float4 q0 = *(const float4*)(qr + lane * 4);
        float4 q1 = make_float4(0.f, 0.f, 0.f, 0.f);
        if (nv > 1) q1 = *(const float4*)(qr + 128 + lane * 4);

        // ---- pass 1: scores + max (4-edge interleaved) ----
        float mx = -FLT_MAX;
        int j = 0;
        for (; j + 3 < deg; j += 4) {
            int s0 = g_ssrc[beg + j];
            int s1 = g_ssrc[beg + j + 1];
            int s2 = g_ssrc[beg + j + 2];
            int s3 = g_ssrc[beg + j + 3];
            const float* k0p = g_k + (size_t)s0 * d;
            const float* k1p = g_k + (size_t)s1 * d;
            const float* k2p = g_k + (size_t)s2 * d;
            const float* k3p = g_k + (size_t)s3 * d;
            float4 b0 = *(const float4*)(k0p + lane * 4);
            float4 c0 = *(const float4*)(k1p + lane * 4);
            float4 d0 = *(const float4*)(k2p + lane * 4);
            float4 f0 = *(const float4*)(k3p + lane * 4);
            float sa = q0.x * b0.x + q0.y * b0.y + q0.z * b0.z + q0.w * b0.w;
            float sb = q0.x * c0.x + q0.y * c0.y + q0.z * c0.z + q0.w * c0.w;
            float sd = q0.x * d0.x + q0.y * d0.y + q0.z * d0.z + q0.w * d0.w;
            float sf = q0.x * f0.x + q0.y * f0.y + q0.z * f0.z + q0.w * f0.w;
            if (nv > 1) {
                float4 b1 = *(const float4*)(k0p + 128 + lane * 4);
                float4 c1 = *(const float4*)(k1p + 128 + lane * 4);
                float4 d1 = *(const float4*)(k2p + 128 + lane * 4);
                float4 f1 = *(const float4*)(k3p + 128 + lane * 4);
                sa += q1.x * b1.x + q1.y * b1.y + q1.z * b1.z + q1.w * b1.w;
                sb += q1.x * c1.x + q1.y * c1.y + q1.z * c1.z + q1.w * c1.w;
                sd += q1.x * d1.x + q1.y * d1.y + q1.z * d1.z + q1.w * d1.w;
                sf += q1.x * f1.x + q1.y * f1.y + q1.z * f1.z + q1.w * f1.w;
            }
#pragma unroll
            for (int o = 16; o; o >>= 1) {
                sa += __shfl_xor_sync(0xFFFFFFFFu, sa, o);
                sb += __shfl_xor_sync(0xFFFFFFFFu, sb, o);
                sd += __shfl_xor_sync(0xFFFFFFFFu, sd, o);
                sf += __shfl_xor_sync(0xFFFFFFFFu, sf, o);
            }
            sa *= inv_sqrt_d;
            sb *= inv_sqrt_d;
            sd *= inv_sqrt_d;
            sf *= inv_sqrt_d;
            mx = fmaxf(mx, fmaxf(fmaxf(sa, sb), fmaxf(sd, sf)));
            if (lane == 0) {
                if (j < DEG_CAP) sc[wIn][j] = sa; else g_score[beg + j] = sa;
                if (j + 1 < DEG_CAP) sc[wIn][j + 1] = sb; else g_score[beg + j + 1] = sb;
                if (j + 2 < DEG_CAP) sc[wIn][j + 2] = sd; else g_score[beg + j + 2] = sd;
                if (j + 3 < DEG_CAP) sc[wIn][j + 3] = sf; else g_score[beg + j + 3] = sf;
            }
        }
        for (; j < deg; j++) {
            int s = g_ssrc[beg + j];
            const float* kr = g_k + (size_t)s * d;
            float4 b0 = *(const float4*)(kr + lane * 4);
            float sum = q0.x * b0.x + q0.y * b0.y + q0.z * b0.z + q0.w * b0.w;
            if (nv > 1) {
                float4 b1 = *(const float4*)(kr + 128 + lane * 4);
                sum += q1.x * b1.x + q1.y * b1.y + q1.z * b1.z + q1.w * b1.w;
            }
#pragma unroll
            for (int o = 16; o; o >>= 1) sum += __shfl_xor_sync(0xFFFFFFFFu, sum, o);
            sum *= inv_sqrt_d;
            mx = fmaxf(mx, sum);
            if (lane == 0) {
                if (j < DEG_CAP) sc[wIn][j] = sum; else g_score[beg + j] = sum;
            }
        }
        __syncwarp();

        // ---- pass 2: exp + denom ----
        float den = 0.f;
        for (int jj = lane; jj < deg; jj += 32) {
            float v = (jj < DEG_CAP) ? sc[wIn][jj] : g_score[beg + jj];
            float e = __expf(v - mx);
            if (jj < DEG_CAP) sc[wIn][jj] = e;
            else g_score[beg + jj] = e;
            den += e;
        }
#pragma unroll
        for (int o = 16; o; o >>= 1) den += __shfl_xor_sync(0xFFFFFFFFu, den, o);
        float rden = 1.f / den;
        __syncwarp();

        // ---- pass 3: weighted aggregate (4-edge unrolled) ----
        j = 0;
        for (; j + 3 < deg; j += 4) {
            int s0 = g_ssrc[beg + j];
            int s1 = g_ssrc[beg + j + 1];
            int s2 = g_ssrc[beg + j + 2];
            int s3 = g_ssrc[beg + j + 3];
            float e0 = (j < DEG_CAP) ? sc[wIn][j] : g_score[beg + j];
            float e1 = (j + 1 < DEG_CAP) ? sc[wIn][j + 1] : g_score[beg + j + 1];
            float e2 = (j + 2 < DEG_CAP) ? sc[wIn][j + 2] : g_score[beg + j + 2];
            float e3 = (j + 3 < DEG_CAP) ? sc[wIn][j + 3] : g_score[beg + j + 3];
            float al0 = e0 * rden, al1 = e1 * rden, al2 = e2 * rden, al3 = e3 * rden;
            const float* v0p = g_v + (size_t)s0 * d;
            const float* v1p = g_v + (size_t)s1 * d;
            const float* v2p = g_v + (size_t)s2 * d;
            const float* v3p = g_v + (size_t)s3 * d;
            float4 b0 = *(const float4*)(v0p + lane * 4);
            float4 c0 = *(const float4*)(v1p + lane * 4);
            float4 d0 = *(const float4*)(v2p + lane * 4);
            float4 f0 = *(const float4*)(v3p + lane * 4);
            a0.x += al0 * b0.x + al1 * c0.x + al2 * d0.x + al3 * f0.x;
            a0.y += al0 * b0.y + al1 * c0.y + al2 * d0.y + al3 * f0.y;
            a0.z += al0 * b0.z + al1 * c0.z + al2 * d0.z + al3 * f0.z;
            a0.w += al0 * b0.w + al1 * c0.w + al2 * d0.w + al3 * f0.w;
            if (nv > 1) {
                float4 b1 = *(const float4*)(v0p + 128 + lane * 4);
                float4 c1 = *(const float4*)(v1p + 128 + lane * 4);
                float4 d1 = *(const float4*)(v2p + 128 + lane * 4);
                float4 f1 = *(const float4*)(v3p + 128 + lane * 4);
                a1.x += al0 * b1.x + al1 * c1.x + al2 * d1.x + al3 * f1.x;
                a1.y += al0 * b1.y + al1 * c1.y + al2 * d1.y + al3 * f1.y;
                a1.z += al0 * b1.z + al1 * c1.z + al2 * d1.z + al3 * f1.z;
                a1.w += al0 * b1.w + al1 * c1.w + al2 * d1.w + al3 * f1.w;
            }
        }
        for (; j < deg; j++) {
            int s = g_ssrc[beg + j];
            float e = (j < DEG_CAP) ? sc[wIn][j] : g_score[beg + j];
            float alpha = e * rden;
            const float* vr = g_v + (size_t)s * d;
            float4 b0 = *(const float4*)(vr + lane * 4);
            a0.x += alpha * b0.x; a0.y += alpha * b0.y;
            a0.z += alpha * b0.z; a0.w += alpha * b0.w;
            if (nv > 1) {
                float4 b1 = *(const float4*)(vr + 128 + lane * 4);
                a1.x += alpha * b1.x; a1.y += alpha * b1.y;
                a1.z += alpha * b1.z; a1.w += alpha * b1.w;
            }
        }
    }

    float* hr = sel(h_sel) + (size_t)gw * d;
    float4 h0 = *(float4*)(hr + lane * 4);
    h0.x += a0.x; h0.y += a0.y; h0.z += a0.z; h0.w += a0.w;
    *(float4*)(hr + lane * 4) = h0;
    float4 h1 = make_float4(0.f, 0.f, 0.f, 0.f);
    if (nv > 1) {
        h1 = *(float4*)(hr + 128 + lane * 4);
        h1.x += a1.x; h1.y += a1.y; h1.z += a1.z; h1.w += a1.w;
        *(float4*)(hr + 128 + lane * 4) = h1;
    }

    if (do_split) {
        __nv_bfloat16* AhP = (__nv_bfloat16*)g_ah4;
        __nv_bfloat16* AlP = (__nv_bfloat16*)g_al4;
        float lx, ly, lz, lw;
        float hx = bf_hi_val(h0.x, lx);
        float hy = bf_hi_val(h0.y, ly);
        float hz = bf_hi_val(h0.z, lz);
        float hw = bf_hi_val(h0.w, lw);
        *(uint2*)(AhP + (size_t)gw * d + lane * 4) = make_uint2(pack_bf(hx, hy), pack_bf(hz, hw));
        *(uint2*)(AlP + (size_t)gw * d + lane * 4) = make_uint2(pack_bf(lx, ly), pack_bf(lz, lw));
        if (nv > 1) {
            float hx1 = bf_hi_val(h1.x, lx);
            float hy1 = bf_hi_val(h1.y, ly);
            float hz1 = bf_hi_val(h1.z, lz);
            float hw1 = bf_hi_val(h1.w, lw);
            *(uint2*)(AhP + (size_t)gw * d + 128 + lane * 4) = make_uint2(pack_bf(hx1, hy1), pack_bf(hz1, hw1));
            *(uint2*)(AlP + (size_t)gw * d + 128 + lane * 4) = make_uint2(pack_bf(lx, ly), pack_bf(lz, lw));
        }
    }
}

// ---------------- pooling ----------------
__global__ void pool_init_kernel() {
    int c = threadIdx.x;
    if (c < 256) {
        g_psum[c] = 0.f;
        g_pmax[c] = ENC_NEG_INF;
    }
}

__global__ void pool_kernel(int M, int d) {
    int c = threadIdx.x;
    const float* h = g_h2;
    float sum = 0.f, mx = -FLT_MAX;
    for (int r = blockIdx.x; r < M; r += gridDim.x) {
        float v = h[(size_t)r * d + c];
        sum += v;
        mx = fmaxf(mx, v);
    }
    atomicAdd(&g_psum[c], sum);
    atomicMax(&g_pmax[c], fenc(mx));
}

__global__ void pool_final_kernel(float* __restrict__ out, int M, int d) {
    int c = threadIdx.x;
    if (c < d) {
        out[c] = g_psum[c] / (float)M;
        out[d + c] = fdec(g_pmax[c]);
    }
}

// ---------------- launch ----------------
extern "C" void kernel_launch(void* const* d_in, const int* in_sizes, int n_in,
                              void* d_out, int out_size) {
    const float* x   = (const float*)d_in[0];
    const void*  ei  = d_in[1];
    const float* Wq1 = (const float*)d_in[3];
    const float* bq1 = (const float*)d_in[4];
    const float* Wk1 = (const float*)d_in[5];
    const float* bk1 = (const float*)d_in[6];
    const float* Wv1 = (const float*)d_in[7];
    const float* bv1 = (const float*)d_in[8];
    const float* Ws1 = (const float*)d_in[9];
    const float* bs1 = (const float*)d_in[10];
    const float* Wq2 = (const float*)d_in[11];
    const float* bq2 = (const float*)d_in[12];
    const float* Wk2 = (const float*)d_in[13];
    const float* bk2 = (const float*)d_in[14];
    const float* Wv2 = (const float*)d_in[15];
    const float* bv2 = (const float*)d_in[16];
    const float* Ws2 = (const float*)d_in[17];
    const float* bs2 = (const float*)d_in[18];
    float* out = (float*)d_out;

    const int D_IN = 512, D_HID = 256, D_OUT = 128;
    int Nn = in_sizes[0] / D_IN;
    int E  = in_sizes[2];

    static int smem_set = 0;
    if (!smem_set) {
        cudaFuncSetAttribute(gemm_mma_kernel,
                             cudaFuncAttributeMaxDynamicSharedMemorySize, GEMM_SMEM);
        smem_set = 1;
    }

    int nb = (Nn + 255) / 256;
    int t4 = Nn * D_IN / 4;

    // stage 1: detect int width + zero degree array
    detect_zero_kernel<<<nb, 256>>>((const unsigned*)ei, E, Nn);

    // stage 2: fused convert + split_a(L1) + split_w(L1) + split_w(L2)
    {
        int bConv = (E + 255) / 256;
        int bA = (t4 + 255) / 256;
        int bW1 = (4 * D_IN * D_HID) / 256;   // 2048
        int bW2 = (4 * D_HID * D_OUT) / 256;  // 512
        int b1 = bConv, b2 = b1 + bA, b3 = b2 + bW1, b4 = b3 + bW2;
        fused_prep_kernel<<<b4, 256>>>(ei, E, x, t4,
                                       Wq1, Wk1, Wv1, Ws1, Wq2, Wk2, Wv2, Ws2,
                                       b1, b2, b3, b4);
    }

    // stage 3: scan + permute
    part_sum_kernel<<<nb, 256>>>(Nn);
    part_scan_kernel<<<1, 256>>>(nb, Nn);
    off_kernel<<<nb, 256>>>(Nn);
    permute_kernel<<<(E + 255) / 256, 256>>>(E);

    int nTiles = (Nn + 127) / 128;
    int edgeBlks = (Nn * 32 + 255) / 256;

    // ===== layer 1 =====
    {
        dim3 g(8, nTiles);
        gemm_mma_kernel<<<g, 256, GEMM_SMEM>>>(
            0, bq1, bk1, bv1, bs1, 0, 1, 2, 3, Nn, D_IN, D_HID);
    }
    edge_fused_kernel<<<edgeBlks, 256>>>(Nn, D_HID, 3,
        (float)(1.0 / sqrt((double)D_HID)), 1);

    // ===== layer 2 =====
    {
        dim3 g(4, nTiles);
        gemm_mma_kernel<<<g, 256, GEMM_SMEM>>>(
            WOFF_L2, bq2, bk2, bv2, bs2, 0, 1, 2, 4, Nn, D_HID, D_OUT);
    }
    edge_fused_kernel<<<edgeBlks, 256>>>(Nn, D_OUT, 4,
        (float)(1.0 / sqrt((double)D_OUT)), 0);

    // ===== pooling =====
    pool_init_kernel<<<1, 256>>>();
    pool_kernel<<<256, D_OUT>>>(Nn, D_OUT);
    pool_final_kernel<<<1, 256>>>(out, Nn, D_OUT);
}

// round 14
// speedup vs baseline: 1.3883x; 1.0148x over previous
#include <cuda_runtime.h>
#include <cuda_bf16.h>
#include <math.h>
#include <float.h>
#include <stdint.h>

#define MAXN 50000
#define MAXE 800000
#define DMAX 256
#define DEG_CAP 64

// ---------------- static device scratch ----------------
__device__ float g_q[(size_t)MAXN * DMAX];
__device__ float g_k[(size_t)MAXN * DMAX];
__device__ float g_v[(size_t)MAXN * DMAX];
__device__ float g_h1[(size_t)MAXN * DMAX];
__device__ float g_h2[(size_t)MAXN * DMAX];
__device__ float g_score[MAXE];
__device__ int g_src[MAXE];
__device__ int g_dst[MAXE];
__device__ int g_ssrc[MAXE];
__device__ int g_deg[MAXN];
__device__ int g_off[MAXN + 1];
__device__ int g_cursor[MAXN];
__device__ int g_part[256];
__device__ int g_is64;
__device__ float g_psum[256];
__device__ unsigned g_pmax[256];

// pre-split bf16 operands
__device__ uint4 g_ah4[(size_t)MAXN * 512 / 8];
__device__ uint4 g_al4[(size_t)MAXN * 512 / 8];
__device__ uint4 g_wh4[81920];
__device__ uint4 g_wl4[81920];
#define WOFF_L2 524288

__device__ __forceinline__ float* sel(int w) {
    switch (w) {
        case 0: return g_q;
        case 1: return g_k;
        case 2: return g_v;
        case 3: return g_h1;
        default: return g_h2;
    }
}

__device__ __forceinline__ unsigned fenc(float f) {
    unsigned u = __float_as_uint(f);
    return (u & 0x80000000u) ? ~u : (u | 0x80000000u);
}
__device__ __forceinline__ float fdec(unsigned u) {
    u = (u & 0x80000000u) ? (u ^ 0x80000000u) : ~u;
    return __uint_as_float(u);
}
#define ENC_NEG_INF 0x007FFFFFu

// ---------------- PTX helpers ----------------
__device__ __forceinline__ uint32_t smem_u32(const void* p) {
    uint32_t a;
    asm("{ .reg .u64 t; cvta.to.shared.u64 t, %1; cvt.u32.u64 %0, t; }" : "=r"(a) : "l"(p));
    return a;
}

__device__ __forceinline__ void ldm_x4(uint32_t& r0, uint32_t& r1, uint32_t& r2, uint32_t& r3,
                                       uint32_t addr) {
    asm volatile("ldmatrix.sync.aligned.m8n8.x4.shared.b16 {%0,%1,%2,%3}, [%4];"
        : "=r"(r0), "=r"(r1), "=r"(r2), "=r"(r3) : "r"(addr));
}

__device__ __forceinline__ void mma_bf16(float* c, const uint32_t* a, const uint32_t* b) {
    asm volatile("mma.sync.aligned.m16n8k16.row.col.f32.bf16.bf16.f32 "
        "{%0,%1,%2,%3}, {%4,%5,%6,%7}, {%8,%9}, {%0,%1,%2,%3};"
        : "+f"(c[0]), "+f"(c[1]), "+f"(c[2]), "+f"(c[3])
        : "r"(a[0]), "r"(a[1]), "r"(a[2]), "r"(a[3]), "r"(b[0]), "r"(b[1]));
}

__device__ __forceinline__ void cp16(uint32_t saddr, const void* gptr, int srcsize) {
    asm volatile("cp.async.ca.shared.global [%0], [%1], 16, %2;"
        :: "r"(saddr), "l"(gptr), "r"(srcsize) : "memory");
}
__device__ __forceinline__ void cp_commit() {
    asm volatile("cp.async.commit_group;" ::: "memory");
}
__device__ __forceinline__ void cp_wait0() {
    asm volatile("cp.async.wait_group 0;" ::: "memory");
}
__device__ __forceinline__ void cp_wait1() {
    asm volatile("cp.async.wait_group 1;" ::: "memory");
}

__device__ __forceinline__ uint32_t pack_bf(float a, float b) {
    __nv_bfloat162 t = __floats2bfloat162_rn(a, b);
    return *(uint32_t*)&t;
}
__device__ __forceinline__ float bf_hi_val(float v, float& lo) {
    __nv_bfloat16 h = __float2bfloat16_rn(v);
    float hf = __bfloat162float(h);
    lo = v - hf;
    return hf;
}

// ---------------- stage 1: detect + zero degrees + pool init ----------------
__global__ void detect_zero_kernel(const unsigned* __restrict__ ei, int E, int Nn) {
    int i = blockIdx.x * blockDim.x + threadIdx.x;
    if (i < Nn) g_deg[i] = 0;
    if (i < 256) {
        g_psum[i] = 0.f;
        g_pmax[i] = ENC_NEG_INF;
    }
    if (i == 0) {
        int n = E < 64 ? E : 64;
        int is64 = 1;
        for (int j = 0; j < n; j++) {
            if (ei[2 * j + 1] != 0u) { is64 = 0; break; }
        }
        g_is64 = is64;
    }
}

// ---------------- stage 2: fused convert + split_a + split_w ----------------
__global__ void fused_prep_kernel(
    const void* __restrict__ ei, int E,
    const float* __restrict__ x, int t4,
    const float* __restrict__ Wq1, const float* __restrict__ Wk1,
    const float* __restrict__ Wv1, const float* __restrict__ Ws1,
    const float* __restrict__ Wq2, const float* __restrict__ Wk2,
    const float* __restrict__ Wv2, const float* __restrict__ Ws2,
    int b1, int b2, int b3, int b4) {
    int blk = blockIdx.x;
    int tid = threadIdx.x;

    if (blk < b1) {
        int i = blk * 256 + tid;
        if (i >= E) return;
        int s, t;
        if (g_is64) {
            const long long* p = (const long long*)ei;
            s = (int)p[i];
            t = (int)p[E + i];
        } else {
            const int* p = (const int*)ei;
            s = p[i];
            t = p[E + i];
        }
        g_src[i] = s;
        g_dst[i] = t;
        atomicAdd(&g_deg[t], 1);
    } else if (blk < b2) {
        int i = (blk - b1) * 256 + tid;
        if (i >= t4) return;
        float4 v = ((const float4*)x)[i];
        if (v.x != v.x) v.x = 0.f;
        if (v.y != v.y) v.y = 0.f;
        if (v.z != v.z) v.z = 0.f;
        if (v.w != v.w) v.w = 0.f;
        float lx, ly, lz, lw;
        float hx = bf_hi_val(v.x, lx);
        float hy = bf_hi_val(v.y, ly);
        float hz = bf_hi_val(v.z, lz);
        float hw = bf_hi_val(v.w, lw);
        ((uint2*)g_ah4)[i] = make_uint2(pack_bf(hx, hy), pack_bf(hz, hw));
        ((uint2*)g_al4)[i] = make_uint2(pack_bf(lx, ly), pack_bf(lz, lw));
    } else if (blk < b3) {
        int j = (blk - b2) * 256 + tid;
        int w = j >> 17;
        int i = j & 131071;
        const float* W = (w == 0) ? Wq1 : (w == 1) ? Wk1 : (w == 2) ? Wv1 : Ws1;
        int k = i >> 8, n = i & 255;
        float v = W[i];
        float lo;
        float hi = bf_hi_val(v, lo);
        size_t o = (size_t)w * 131072 + (size_t)n * 512 + k;
        ((__nv_bfloat16*)g_wh4)[o] = __float2bfloat16_rn(hi);
        ((__nv_bfloat16*)g_wl4)[o] = __float2bfloat16_rn(lo);
    } else if (blk < b4) {
        int j = (blk - b3) * 256 + tid;
        int w = j >> 15;
        int i = j & 32767;
        const float* W = (w == 0) ? Wq2 : (w == 1) ? Wk2 : (w == 2) ? Wv2 : Ws2;
        int k = i >> 7, n = i & 127;
        float v = W[i];
        float lo;
        float hi = bf_hi_val(v, lo);
        size_t o = (size_t)WOFF_L2 + (size_t)w * 32768 + (size_t)n * 256 + k;
        ((__nv_bfloat16*)g_wh4)[o] = __float2bfloat16_rn(hi);
        ((__nv_bfloat16*)g_wl4)[o] = __float2bfloat16_rn(lo);
    }
}

// ---------------- scan + permute ----------------
__global__ void part_sum_kernel(int Nn) {
    __shared__ int red[256];
    int t = threadIdx.x;
    int i = blockIdx.x * 256 + t;
    red[t] = (i < Nn) ? g_deg[i] : 0;
    __syncthreads();
    for (int o = 128; o; o >>= 1) {
        if (t < o) red[t] += red[t + o];
        __syncthreads();
    }
    if (t == 0) g_part[blockIdx.x] = red[0];
}

__global__ void part_scan_kernel(int nb, int Nn) {
    __shared__ int s[256];
    int t = threadIdx.x;
    s[t] = (t < nb) ? g_part[t] : 0;
    __syncthreads();
    for (int o = 1; o < 256; o <<= 1) {
        int u = (t >= o) ? s[t - o] : 0;
        __syncthreads();
        s[t] += u;
        __syncthreads();
    }
    g_part[t] = (t > 0) ? s[t - 1] : 0;
    if (t == 255) g_off[Nn] = s[255];
}

__global__ void off_kernel(int Nn) {
    __shared__ int s[256];
    int t = threadIdx.x;
    int i = blockIdx.x * 256 + t;
    int v = (i < Nn) ? g_deg[i] : 0;
    s[t] = v;
    __syncthreads();
    for (int o = 1; o < 256; o <<= 1) {
        int u = (t >= o) ? s[t - o] : 0;
        __syncthreads();
        s[t] += u;
        __syncthreads();
    }
    if (i < Nn) {
        int excl = s[t] - v + g_part[blockIdx.x];
        g_off[i] = excl;
        g_cursor[i] = excl;
    }
}

__global__ void permute_kernel(int E) {
    int i = blockIdx.x * blockDim.x + threadIdx.x;
    if (i >= E) return;
    int t = g_dst[i];
    int pos = atomicAdd(&g_cursor[t], 1);
    g_ssrc[pos] = g_src[i];
}

// ================= bf16 mma.sync GEMM, cp.async pipeline, occ 2 =================
#define OFF_AH 0
#define OFF_AL 10240
#define OFF_BH 20480
#define OFF_BL 30720
#define BUF_SZ 40960
#define GEMM_SMEM (2 * BUF_SZ)

__global__ __launch_bounds__(256, 2)
void gemm_mma_kernel(int wbase,
                     const float* __restrict__ b0, const float* __restrict__ b1,
                     const float* __restrict__ b2, const float* __restrict__ b3,
                     int c0, int c1, int c2, int c3,
                     int M, int K, int Nt) {
    extern __shared__ char smem[];
    const uint32_t sbase = smem_u32(smem);

    const int tid = threadIdx.x;
    const int wid = tid >> 5;
    const int lid = tid & 31;
    const int wm = wid & 1;
    const int wn = wid >> 1;
    const int rowBase = blockIdx.y * 128;

    const int cbPerW = Nt >> 7;
    const int wsel = blockIdx.x / cbPerW;
    const int colBase = (blockIdx.x - wsel * cbPerW) * 128;

    const __nv_bfloat16* Ah = (const __nv_bfloat16*)g_ah4;
    const __nv_bfloat16* Al = (const __nv_bfloat16*)g_al4;
    const __nv_bfloat16* Wh = (const __nv_bfloat16*)g_wh4 + (size_t)wbase + (size_t)wsel * K * Nt;
    const __nv_bfloat16* Wl = (const __nv_bfloat16*)g_wl4 + (size_t)wbase + (size_t)wsel * K * Nt;

    const float* bias;
    int csel;
    switch (wsel) {
        case 0: bias = b0; csel = c0; break;
        case 1: bias = b1; csel = c1; break;
        case 2: bias = b2; csel = c2; break;
        default: bias = b3; csel = c3; break;
    }
    float* C = sel(csel);

    float acc[4][4][4];
#pragma unroll
    for (int i = 0; i < 4; i++)
#pragma unroll
        for (int j = 0; j < 4; j++)
#pragma unroll
            for (int q = 0; q < 4; q++) acc[i][j][q] = 0.f;

    const int l_row = tid >> 2;
    const int l_kq = tid & 3;
    const int nChunks = K >> 5;

    const int grow0 = rowBase + l_row;
    const int grow1 = rowBase + l_row + 64;
    const int a_ok0 = (grow0 < M) ? 16 : 0;
    const int a_ok1 = (grow1 < M) ? 16 : 0;
    const int n0 = colBase + l_row;
    const int n1 = colBase + l_row + 64;
    const uint32_t soff0 = (uint32_t)(l_row * 80 + l_kq * 16);
    const uint32_t soff1 = soff0 + 64 * 80;

    auto issue = [&](int c, int b) {
        const int k0 = c << 5;
        uint32_t bb = sbase + b * BUF_SZ;
        cp16(bb + OFF_AH + soff0, Ah + (size_t)grow0 * K + k0 + l_kq * 8, a_ok0);
        cp16(bb + OFF_AL + soff0, Al + (size_t)grow0 * K + k0 + l_kq * 8, a_ok0);
        cp16(bb + OFF_AH + soff1, Ah + (size_t)grow1 * K + k0 + l_kq * 8, a_ok1);
        cp16(bb + OFF_AL + soff1, Al + (size_t)grow1 * K + k0 + l_kq * 8, a_ok1);
        cp16(bb + OFF_BH + soff0, Wh + (size_t)n0 * K + k0 + l_kq * 8, 16);
        cp16(bb + OFF_BL + soff0, Wl + (size_t)n0 * K + k0 + l_kq * 8, 16);
        cp16(bb + OFF_BH + soff1, Wh + (size_t)n1 * K + k0 + l_kq * 8, 16);
        cp16(bb + OFF_BL + soff1, Wl + (size_t)n1 * K + k0 + l_kq * 8, 16);
        cp_commit();
    };

    issue(0, 0);

    int buf = 0;
    for (int c = 0; c < nChunks; c++) {
        if (c + 1 < nChunks) {
            issue(c + 1, buf ^ 1);
            cp_wait1();
        } else {
            cp_wait0();
        }
        __syncthreads();

        uint32_t bb = sbase + buf * BUF_SZ;
        const int lr = lid & 15;
        const int lc = lid >> 4;
        uint32_t AHB = bb + OFF_AH, ALB = bb + OFF_AL;
        uint32_t BHB = bb + OFF_BH, BLB = bb + OFF_BL;
#pragma unroll
        for (int ks = 0; ks < 2; ks++) {
            uint32_t koff = (uint32_t)(ks * 32 + lc * 16);
            uint32_t ah[4][4], al[4][4], bh[4][2], bl[4][2];
#pragma unroll
            for (int i = 0; i < 4; i++) {
                uint32_t ro = (uint32_t)((wm * 64 + i * 16 + lr) * 80) + koff;
                ldm_x4(ah[i][0], ah[i][1], ah[i][2], ah[i][3], AHB + ro);
                ldm_x4(al[i][0], al[i][1], al[i][2], al[i][3], ALB + ro);
            }
#pragma unroll
            for (int j2 = 0; j2 < 2; j2++) {
                uint32_t ro = (uint32_t)((wn * 32 + j2 * 16 + lr) * 80) + koff;
                uint32_t r0, r1, r2, r3;
                ldm_x4(r0, r1, r2, r3, BHB + ro);
                bh[j2 * 2 + 0][0] = r0; bh[j2 * 2 + 0][1] = r2;
                bh[j2 * 2 + 1][0] = r1; bh[j2 * 2 + 1][1] = r3;
                ldm_x4(r0, r1, r2, r3, BLB + ro);
                bl[j2 * 2 + 0][0] = r0; bl[j2 * 2 + 0][1] = r2;
                bl[j2 * 2 + 1][0] = r1; bl[j2 * 2 + 1][1] = r3;
            }
#pragma unroll
            for (int i = 0; i < 4; i++)
#pragma unroll
                for (int j = 0; j < 4; j++) {
                    mma_bf16(acc[i][j], ah[i], bh[j]);
                    mma_bf16(acc[i][j], ah[i], bl[j]);
                    mma_bf16(acc[i][j], al[i], bh[j]);
                }
        }
        __syncthreads();
        buf ^= 1;
    }

    const int lr4 = lid >> 2;
    const int lc2 = (lid & 3) * 2;
#pragma unroll
    for (int j = 0; j < 4; j++) {
        int gc = colBase + wn * 32 + j * 8 + lc2;
        float bi0 = bias[gc], bi1 = bias[gc + 1];
#pragma unroll
        for (int i = 0; i < 4; i++) {
            int gr0 = rowBase + wm * 64 + i * 16 + lr4;
            int gr1 = gr0 + 8;
            if (gr0 < M) {
                float2 o = make_float2(acc[i][j][0] + bi0, acc[i][j][1] + bi1);
                *(float2*)(C + (size_t)gr0 * Nt + gc) = o;
            }
            if (gr1 < M) {
                float2 o = make_float2(acc[i][j][2] + bi0, acc[i][j][3] + bi1);
                *(float2*)(C + (size_t)gr1 * Nt + gc) = o;
            }
        }
    }
}

// ================= fused per-node edge kernel (two-pass) =================
__global__ __launch_bounds__(256)
void edge_fused_kernel(int Nn, int d, int h_sel, float inv_sqrt_d, int do_split) {
    __shared__ float sc[8][DEG_CAP];
    int gw = (blockIdx.x * blockDim.x + threadIdx.x) >> 5;
    int lane = threadIdx.x & 31;
    int wIn = threadIdx.x >> 5;
    if (gw >= Nn) return;
    int beg = g_off[gw];
    int deg = g_off[gw + 1] - beg;

    const int nv = d >> 7;
    float4 a0 = make_float4(0.f, 0.f, 0.f, 0.f);
    float4 a1 = make_float4(0.f, 0.f, 0.f, 0.f);

    if (deg > 0) {
        const float* qr = g_q + (size_t)gw * d;
        float4 q0 = *(const float4*)(qr + lane * 4);
        float4 q1 = make_float4(0.f, 0.f, 0.f, 0.f);
        if (nv > 1) q1 = *(const float4*)(qr + 128 + lane * 4);

        // ---- pass 1: scores + max (2-edge pipelined) ----
        float mx = -FLT_MAX;
        int j = 0;
        for (; j + 1 < deg; j += 2) {
            int s0 = g_ssrc[beg + j];
            int s1 = g_ssrc[beg + j + 1];
            const float* k0p = g_k + (size_t)s0 * d;
            const float* k1p = g_k + (size_t)s1 * d;
            float4 b0 = *(const float4*)(k0p + lane * 4);
            float4 c0 = *(const float4*)(k1p + lane * 4);
            float sa = q0.x * b0.x + q0.y * b0.y + q0.z * b0.z + q0.w * b0.w;
            float sb = q0.x * c0.x + q0.y * c0.y + q0.z * c0.z + q0.w * c0.w;
            if (nv > 1) {
                float4 b1 = *(const float4*)(k0p + 128 + lane * 4);
                float4 c1 = *(const float4*)(k1p + 128 + lane * 4);
                sa += q1.x * b1.x + q1.y * b1.y + q1.z * b1.z + q1.w * b1.w;
                sb += q1.x * c1.x + q1.y * c1.y + q1.z * c1.z + q1.w * c1.w;
            }
#pragma unroll
            for (int o = 16; o; o >>= 1) {
                sa += __shfl_xor_sync(0xFFFFFFFFu, sa, o);
                sb += __shfl_xor_sync(0xFFFFFFFFu, sb, o);
            }
            sa *= inv_sqrt_d;
            sb *= inv_sqrt_d;
            mx = fmaxf(mx, fmaxf(sa, sb));
            if (lane == 0) {
                if (j < DEG_CAP) sc[wIn][j] = sa; else g_score[beg + j] = sa;
                if (j + 1 < DEG_CAP) sc[wIn][j + 1] = sb; else g_score[beg + j + 1] = sb;
            }
        }
        if (j < deg) {
            int s = g_ssrc[beg + j];
            const float* kr = g_k + (size_t)s * d;
            float4 b0 = *(const float4*)(kr + lane * 4);
            float sum = q0.x * b0.x + q0.y * b0.y + q0.z * b0.z + q0.w * b0.w;
            if (nv > 1) {
                float4 b1 = *(const float4*)(kr + 128 + lane * 4);
                sum += q1.x * b1.x + q1.y * b1.y + q1.z * b1.z + q1.w * b1.w;
            }
#pragma unroll
            for (int o = 16; o; o >>= 1) sum += __shfl_xor_sync(0xFFFFFFFFu, sum, o);
            sum *= inv_sqrt_d;
            mx = fmaxf(mx, sum);
            if (lane == 0) {
                if (j < DEG_CAP) sc[wIn][j] = sum; else g_score[beg + j] = sum;
            }
        }
        __syncwarp();

        // ---- pass 2: exp + denom ----
        float den = 0.f;
        for (int jj = lane; jj < deg; jj += 32) {
            float v = (jj < DEG_CAP) ? sc[wIn][jj] : g_score[beg + jj];
            float e = __expf(v - mx);
            if (jj < DEG_CAP) sc[wIn][jj] = e;
            else g_score[beg + jj] = e;
            den += e;
        }
#pragma unroll
        for (int o = 16; o; o >>= 1) den += __shfl_xor_sync(0xFFFFFFFFu, den, o);
        float rden = 1.f / den;
        __syncwarp();

        // ---- pass 3: weighted aggregate (4-edge unrolled) ----
        j = 0;
        for (; j + 3 < deg; j += 4) {
            int s0 = g_ssrc[beg + j];
            int s1 = g_ssrc[beg + j + 1];
            int s2 = g_ssrc[beg + j + 2];
            int s3 = g_ssrc[beg + j + 3];
            float e0 = (j < DEG_CAP) ? sc[wIn][j] : g_score[beg + j];
            float e1 = (j + 1 < DEG_CAP) ? sc[wIn][j + 1] : g_score[beg + j + 1];
            float e2 = (j + 2 < DEG_CAP) ? sc[wIn][j + 2] : g_score[beg + j + 2];
            float e3 = (j + 3 < DEG_CAP) ? sc[wIn][j + 3] : g_score[beg + j + 3];
            float al0 = e0 * rden, al1 = e1 * rden, al2 = e2 * rden, al3 = e3 * rden;
            const float* v0p = g_v + (size_t)s0 * d;
            const float* v1p = g_v + (size_t)s1 * d;
            const float* v2p = g_v + (size_t)s2 * d;
            const float* v3p = g_v + (size_t)s3 * d;
            float4 b0 = *(const float4*)(v0p + lane * 4);
            float4 c0 = *(const float4*)(v1p + lane * 4);
            float4 d0 = *(const float4*)(v2p + lane * 4);
            float4 f0 = *(const float4*)(v3p + lane * 4);
            a0.x += al0 * b0.x + al1 * c0.x + al2 * d0.x + al3 * f0.x;
            a0.y += al0 * b0.y + al1 * c0.y + al2 * d0.y + al3 * f0.y;
            a0.z += al0 * b0.z + al1 * c0.z + al2 * d0.z + al3 * f0.z;
            a0.w += al0 * b0.w + al1 * c0.w + al2 * d0.w + al3 * f0.w;
            if (nv > 1) {
                float4 b1 = *(const float4*)(v0p + 128 + lane * 4);
                float4 c1 = *(const float4*)(v1p + 128 + lane * 4);
                float4 d1 = *(const float4*)(v2p + 128 + lane * 4);
                float4 f1 = *(const float4*)(v3p + 128 + lane * 4);
                a1.x += al0 * b1.x + al1 * c1.x + al2 * d1.x + al3 * f1.x;
                a1.y += al0 * b1.y + al1 * c1.y + al2 * d1.y + al3 * f1.y;
                a1.z += al0 * b1.z + al1 * c1.z + al2 * d1.z + al3 * f1.z;
                a1.w += al0 * b1.w + al1 * c1.w + al2 * d1.w + al3 * f1.w;
            }
        }
        for (; j < deg; j++) {
            int s = g_ssrc[beg + j];
            float e = (j < DEG_CAP) ? sc[wIn][j] : g_score[beg + j];
            float alpha = e * rden;
            const float* vr = g_v + (size_t)s * d;
            float4 b0 = *(const float4*)(vr + lane * 4);
            a0.x += alpha * b0.x; a0.y += alpha * b0.y;
            a0.z += alpha * b0.z; a0.w += alpha * b0.w;
            if (nv > 1) {
                float4 b1 = *(const float4*)(vr + 128 + lane * 4);
                a1.x += alpha * b1.x; a1.y += alpha * b1.y;
                a1.z += alpha * b1.z; a1.w += alpha * b1.w;
            }
        }
    }

    float* hr = sel(h_sel) + (size_t)gw * d;
    float4 h0 = *(float4*)(hr + lane * 4);
    h0.x += a0.x; h0.y += a0.y; h0.z += a0.z; h0.w += a0.w;
    *(float4*)(hr + lane * 4) = h0;
    float4 h1 = make_float4(0.f, 0.f, 0.f, 0.f);
    if (nv > 1) {
        h1 = *(float4*)(hr + 128 + lane * 4);
        h1.x += a1.x; h1.y += a1.y; h1.z += a1.z; h1.w += a1.w;
        *(float4*)(hr + 128 + lane * 4) = h1;
    }

    if (do_split) {
        __nv_bfloat16* AhP = (__nv_bfloat16*)g_ah4;
        __nv_bfloat16* AlP = (__nv_bfloat16*)g_al4;
        float lx, ly, lz, lw;
        float hx = bf_hi_val(h0.x, lx);
        float hy = bf_hi_val(h0.y, ly);
        float hz = bf_hi_val(h0.z, lz);
        float hw = bf_hi_val(h0.w, lw);
        *(uint2*)(AhP + (size_t)gw * d + lane * 4) = make_uint2(pack_bf(hx, hy), pack_bf(hz, hw));
        *(uint2*)(AlP + (size_t)gw * d + lane * 4) = make_uint2(pack_bf(lx, ly), pack_bf(lz, lw));
        if (nv > 1) {
            float hx1 = bf_hi_val(h1.x, lx);
            float hy1 = bf_hi_val(h1.y, ly);
            float hz1 = bf_hi_val(h1.z, lz);
            float hw1 = bf_hi_val(h1.w, lw);
            *(uint2*)(AhP + (size_t)gw * d + 128 + lane * 4) = make_uint2(pack_bf(hx1, hy1), pack_bf(hz1, hw1));
            *(uint2*)(AlP + (size_t)gw * d + 128 + lane * 4) = make_uint2(pack_bf(lx, ly), pack_bf(lz, lw));
        }
    }
}

// ---------------- pooling ----------------
__global__ void pool_kernel(int M, int d) {
    int c = threadIdx.x;
    const float* h = g_h2;
    float sum = 0.f, mx = -FLT_MAX;
    for (int r = blockIdx.x; r < M; r += gridDim.x) {
        float v = h[(size_t)r * d + c];
        sum += v;
        mx = fmaxf(mx, v);
    }
    atomicAdd(&g_psum[c], sum);
    atomicMax(&g_pmax[c], fenc(mx));
}

__global__ void pool_final_kernel(float* __restrict__ out, int M, int d) {
    int c = threadIdx.x;
    if (c < d) {
        out[c] = g_psum[c] / (float)M;
        out[d + c] = fdec(g_pmax[c]);
    }
}

// ---------------- launch ----------------
extern "C" void kernel_launch(void* const* d_in, const int* in_sizes, int n_in,
                              void* d_out, int out_size) {
    const float* x   = (const float*)d_in[0];
    const void*  ei  = d_in[1];
    const float* Wq1 = (const float*)d_in[3];
    const float* bq1 = (const float*)d_in[4];
    const float* Wk1 = (const float*)d_in[5];
    const float* bk1 = (const float*)d_in[6];
    const float* Wv1 = (const float*)d_in[7];
    const float* bv1 = (const float*)d_in[8];
    const float* Ws1 = (const float*)d_in[9];
    const float* bs1 = (const float*)d_in[10];
    const float* Wq2 = (const float*)d_in[11];
    const float* bq2 = (const float*)d_in[12];
    const float* Wk2 = (const float*)d_in[13];
    const float* bk2 = (const float*)d_in[14];
    const float* Wv2 = (const float*)d_in[15];
    const float* bv2 = (const float*)d_in[16];
    const float* Ws2 = (const float*)d_in[17];
    const float* bs2 = (const float*)d_in[18];
    float* out = (float*)d_out;

    const int D_IN = 512, D_HID = 256, D_OUT = 128;
    int Nn = in_sizes[0] / D_IN;
    int E  = in_sizes[2];

    // one-time resource setup (outside graph capture; first call is the
    // correctness run which is not captured)
    static cudaStream_t s2 = nullptr;
    static cudaEvent_t evFork = nullptr, evJoin = nullptr;
    if (!s2) {
        cudaFuncSetAttribute(gemm_mma_kernel,
                             cudaFuncAttributeMaxDynamicSharedMemorySize, GEMM_SMEM);
        cudaStreamCreateWithFlags(&s2, cudaStreamNonBlocking);
        cudaEventCreateWithFlags(&evFork, cudaEventDisableTiming);
        cudaEventCreateWithFlags(&evJoin, cudaEventDisableTiming);
    }

    int nb = (Nn + 255) / 256;
    int t4 = Nn * D_IN / 4;

    // stage 1: detect + zero degrees + pool init
    detect_zero_kernel<<<nb, 256>>>((const unsigned*)ei, E, Nn);

    // stage 2: fused convert + splits
    {
        int bConv = (E + 255) / 256;
        int bA = (t4 + 255) / 256;
        int bW1 = (4 * D_IN * D_HID) / 256;
        int bW2 = (4 * D_HID * D_OUT) / 256;
        int b1 = bConv, b2 = b1 + bA, b3 = b2 + bW1, b4 = b3 + bW2;
        fused_prep_kernel<<<b4, 256>>>(ei, E, x, t4,
                                       Wq1, Wk1, Wv1, Ws1, Wq2, Wk2, Wv2, Ws2,
                                       b1, b2, b3, b4);
    }

    // ---- fork: CSR build on side stream, overlapped with layer-1 GEMM ----
    cudaEventRecord(evFork, 0);
    cudaStreamWaitEvent(s2, evFork, 0);
    part_sum_kernel<<<nb, 256, 0, s2>>>(Nn);
    part_scan_kernel<<<1, 256, 0, s2>>>(nb, Nn);
    off_kernel<<<nb, 256, 0, s2>>>(Nn);
    permute_kernel<<<(E + 255) / 256, 256, 0, s2>>>(E);
    cudaEventRecord(evJoin, s2);

    int nTiles = (Nn + 127) / 128;
    int edgeBlks = (Nn * 32 + 255) / 256;

    // layer-1 GEMM on main stream (concurrent with CSR build)
    {
        dim3 g(8, nTiles);
        gemm_mma_kernel<<<g, 256, GEMM_SMEM>>>(
            0, bq1, bk1, bv1, bs1, 0, 1, 2, 3, Nn, D_IN, D_HID);
    }

    // join before edge phase
    cudaStreamWaitEvent(0, evJoin, 0);
    edge_fused_kernel<<<edgeBlks, 256>>>(Nn, D_HID, 3,
        (float)(1.0 / sqrt((double)D_HID)), 1);

    // ===== layer 2 =====
    {
        dim3 g(4, nTiles);
        gemm_mma_kernel<<<g, 256, GEMM_SMEM>>>(
            WOFF_L2, bq2, bk2, bv2, bs2, 0, 1, 2, 4, Nn, D_HID, D_OUT);
    }
    edge_fused_kernel<<<edgeBlks, 256>>>(Nn, D_OUT, 4,
        (float)(1.0 / sqrt((double)D_OUT)), 0);

    // ===== pooling =====
    pool_kernel<<<256, D_OUT>>>(Nn, D_OUT);
    pool_final_kernel<<<1, 256>>>(out, Nn, D_OUT);
}

// round 15
// speedup vs baseline: 1.5101x; 1.0877x over previous
#include <cuda_runtime.h>
#include <cuda_bf16.h>
#include <math.h>
#include <float.h>
#include <stdint.h>

#define MAXN 50000
#define MAXE 800000
#define DMAX 256
#define DEG_CAP 64

// ---------------- static device scratch ----------------
__device__ float g_q[(size_t)MAXN * DMAX];
__device__ float g_k[(size_t)MAXN * DMAX];
__device__ float g_v[(size_t)MAXN * DMAX];
__device__ float g_h1[(size_t)MAXN * DMAX];
__device__ float g_h2[(size_t)MAXN * DMAX];
__device__ float g_score[MAXE];
__device__ int g_src[MAXE];
__device__ int g_dst[MAXE];
__device__ int g_ssrc[MAXE];
__device__ int g_deg[MAXN];
__device__ int g_off[MAXN + 1];
__device__ int g_cursor[MAXN];
__device__ int g_part[256];
__device__ int g_is64;
__device__ float g_psum[256];
__device__ unsigned g_pmax[256];

// pre-split bf16 operands
__device__ uint4 g_ah4[(size_t)MAXN * 512 / 8];
__device__ uint4 g_al4[(size_t)MAXN * 512 / 8];
__device__ uint4 g_wh4[81920];
__device__ uint4 g_wl4[81920];
#define WOFF_L2 524288

__device__ __forceinline__ float* sel(int w) {
    switch (w) {
        case 0: return g_q;
        case 1: return g_k;
        case 2: return g_v;
        case 3: return g_h1;
        default: return g_h2;
    }
}

__device__ __forceinline__ unsigned fenc(float f) {
    unsigned u = __float_as_uint(f);
    return (u & 0x80000000u) ? ~u : (u | 0x80000000u);
}
__device__ __forceinline__ float fdec(unsigned u) {
    u = (u & 0x80000000u) ? (u ^ 0x80000000u) : ~u;
    return __uint_as_float(u);
}
#define ENC_NEG_INF 0x007FFFFFu

// ---------------- PTX helpers ----------------
__device__ __forceinline__ uint32_t smem_u32(const void* p) {
    uint32_t a;
    asm("{ .reg .u64 t; cvta.to.shared.u64 t, %1; cvt.u32.u64 %0, t; }" : "=r"(a) : "l"(p));
    return a;
}

__device__ __forceinline__ void ldm_x4(uint32_t& r0, uint32_t& r1, uint32_t& r2, uint32_t& r3,
                                       uint32_t addr) {
    asm volatile("ldmatrix.sync.aligned.m8n8.x4.shared.b16 {%0,%1,%2,%3}, [%4];"
        : "=r"(r0), "=r"(r1), "=r"(r2), "=r"(r3) : "r"(addr));
}

__device__ __forceinline__ void mma_bf16(float* c, const uint32_t* a, const uint32_t* b) {
    asm volatile("mma.sync.aligned.m16n8k16.row.col.f32.bf16.bf16.f32 "
        "{%0,%1,%2,%3}, {%4,%5,%6,%7}, {%8,%9}, {%0,%1,%2,%3};"
        : "+f"(c[0]), "+f"(c[1]), "+f"(c[2]), "+f"(c[3])
        : "r"(a[0]), "r"(a[1]), "r"(a[2]), "r"(a[3]), "r"(b[0]), "r"(b[1]));
}

__device__ __forceinline__ void cp16(uint32_t saddr, const void* gptr, int srcsize) {
    asm volatile("cp.async.ca.shared.global [%0], [%1], 16, %2;"
        :: "r"(saddr), "l"(gptr), "r"(srcsize) : "memory");
}
__device__ __forceinline__ void cp_commit() {
    asm volatile("cp.async.commit_group;" ::: "memory");
}
__device__ __forceinline__ void cp_wait0() {
    asm volatile("cp.async.wait_group 0;" ::: "memory");
}
__device__ __forceinline__ void cp_wait1() {
    asm volatile("cp.async.wait_group 1;" ::: "memory");
}

__device__ __forceinline__ uint32_t pack_bf(float a, float b) {
    __nv_bfloat162 t = __floats2bfloat162_rn(a, b);
    return *(uint32_t*)&t;
}
__device__ __forceinline__ float bf_hi_val(float v, float& lo) {
    __nv_bfloat16 h = __float2bfloat16_rn(v);
    float hf = __bfloat162float(h);
    lo = v - hf;
    return hf;
}

// ---------------- s2 stage 1: detect + zero degrees + pool init ----------------
__global__ void detect_zero_kernel(const unsigned* __restrict__ ei, int E, int Nn) {
    int i = blockIdx.x * blockDim.x + threadIdx.x;
    if (i < Nn) g_deg[i] = 0;
    if (i < 256) {
        g_psum[i] = 0.f;
        g_pmax[i] = ENC_NEG_INF;
    }
    if (i == 0) {
        int n = E < 64 ? E : 64;
        int is64 = 1;
        for (int j = 0; j < n; j++) {
            if (ei[2 * j + 1] != 0u) { is64 = 0; break; }
        }
        g_is64 = is64;
    }
}

// ---------------- s2 stage 2: edge index convert + degree histogram ----------------
__global__ void convert_kernel(const void* __restrict__ ei, int E) {
    int i = blockIdx.x * blockDim.x + threadIdx.x;
    if (i >= E) return;
    int s, t;
    if (g_is64) {
        const long long* p = (const long long*)ei;
        s = (int)p[i];
        t = (int)p[E + i];
    } else {
        const int* p = (const int*)ei;
        s = p[i];
        t = p[E + i];
    }
    g_src[i] = s;
    g_dst[i] = t;
    atomicAdd(&g_deg[t], 1);
}

// ---------------- main stage 1: fused split_a + split_w ----------------
__global__ void fused_split_kernel(
    const float* __restrict__ x, int t4,
    const float* __restrict__ Wq1, const float* __restrict__ Wk1,
    const float* __restrict__ Wv1, const float* __restrict__ Ws1,
    const float* __restrict__ Wq2, const float* __restrict__ Wk2,
    const float* __restrict__ Wv2, const float* __restrict__ Ws2,
    int b1, int b2, int b3) {
    int blk = blockIdx.x;
    int tid = threadIdx.x;

    if (blk < b1) {
        int i = blk * 256 + tid;
        if (i >= t4) return;
        float4 v = ((const float4*)x)[i];
        if (v.x != v.x) v.x = 0.f;
        if (v.y != v.y) v.y = 0.f;
        if (v.z != v.z) v.z = 0.f;
        if (v.w != v.w) v.w = 0.f;
        float lx, ly, lz, lw;
        float hx = bf_hi_val(v.x, lx);
        float hy = bf_hi_val(v.y, ly);
        float hz = bf_hi_val(v.z, lz);
        float hw = bf_hi_val(v.w, lw);
        ((uint2*)g_ah4)[i] = make_uint2(pack_bf(hx, hy), pack_bf(hz, hw));
        ((uint2*)g_al4)[i] = make_uint2(pack_bf(lx, ly), pack_bf(lz, lw));
    } else if (blk < b2) {
        int j = (blk - b1) * 256 + tid;
        int w = j >> 17;
        int i = j & 131071;
        const float* W = (w == 0) ? Wq1 : (w == 1) ? Wk1 : (w == 2) ? Wv1 : Ws1;
        int k = i >> 8, n = i & 255;
        float v = W[i];
        float lo;
        float hi = bf_hi_val(v, lo);
        size_t o = (size_t)w * 131072 + (size_t)n * 512 + k;
        ((__nv_bfloat16*)g_wh4)[o] = __float2bfloat16_rn(hi);
        ((__nv_bfloat16*)g_wl4)[o] = __float2bfloat16_rn(lo);
    } else if (blk < b3) {
        int j = (blk - b2) * 256 + tid;
        int w = j >> 15;
        int i = j & 32767;
        const float* W = (w == 0) ? Wq2 : (w == 1) ? Wk2 : (w == 2) ? Wv2 : Ws2;
        int k = i >> 7, n = i & 127;
        float v = W[i];
        float lo;
        float hi = bf_hi_val(v, lo);
        size_t o = (size_t)WOFF_L2 + (size_t)w * 32768 + (size_t)n * 256 + k;
        ((__nv_bfloat16*)g_wh4)[o] = __float2bfloat16_rn(hi);
        ((__nv_bfloat16*)g_wl4)[o] = __float2bfloat16_rn(lo);
    }
}

// ---------------- scan + permute ----------------
__global__ void part_sum_kernel(int Nn) {
    __shared__ int red[256];
    int t = threadIdx.x;
    int i = blockIdx.x * 256 + t;
    red[t] = (i < Nn) ? g_deg[i] : 0;
    __syncthreads();
    for (int o = 128; o; o >>= 1) {
        if (t < o) red[t] += red[t + o];
        __syncthreads();
    }
    if (t == 0) g_part[blockIdx.x] = red[0];
}

__global__ void part_scan_kernel(int nb, int Nn) {
    __shared__ int s[256];
    int t = threadIdx.x;
    s[t] = (t < nb) ? g_part[t] : 0;
    __syncthreads();
    for (int o = 1; o < 256; o <<= 1) {
        int u = (t >= o) ? s[t - o] : 0;
        __syncthreads();
        s[t] += u;
        __syncthreads();
    }
    g_part[t] = (t > 0) ? s[t - 1] : 0;
    if (t == 255) g_off[Nn] = s[255];
}

__global__ void off_kernel(int Nn) {
    __shared__ int s[256];
    int t = threadIdx.x;
    int i = blockIdx.x * 256 + t;
    int v = (i < Nn) ? g_deg[i] : 0;
    s[t] = v;
    __syncthreads();
    for (int o = 1; o < 256; o <<= 1) {
        int u = (t >= o) ? s[t - o] : 0;
        __syncthreads();
        s[t] += u;
        __syncthreads();
    }
    if (i < Nn) {
        int excl = s[t] - v + g_part[blockIdx.x];
        g_off[i] = excl;
        g_cursor[i] = excl;
    }
}

__global__ void permute_kernel(int E) {
    int i = blockIdx.x * blockDim.x + threadIdx.x;
    if (i >= E) return;
    int t = g_dst[i];
    int pos = atomicAdd(&g_cursor[t], 1);
    g_ssrc[pos] = g_src[i];
}

// ================= bf16 mma.sync GEMM, cp.async pipeline, occ 2 =================
#define OFF_AH 0
#define OFF_AL 10240
#define OFF_BH 20480
#define OFF_BL 30720
#define BUF_SZ 40960
#define GEMM_SMEM (2 * BUF_SZ)

__global__ __launch_bounds__(256, 2)
void gemm_mma_kernel(int wbase,
                     const float* __restrict__ b0, const float* __restrict__ b1,
                     const float* __restrict__ b2, const float* __restrict__ b3,
                     int c0, int c1, int c2, int c3,
                     int M, int K, int Nt) {
    extern __shared__ char smem[];
    const uint32_t sbase = smem_u32(smem);

    const int tid = threadIdx.x;
    const int wid = tid >> 5;
    const int lid = tid & 31;
    const int wm = wid & 1;
    const int wn = wid >> 1;
    const int rowBase = blockIdx.y * 128;

    const int cbPerW = Nt >> 7;
    const int wsel = blockIdx.x / cbPerW;
    const int colBase = (blockIdx.x - wsel * cbPerW) * 128;

    const __nv_bfloat16* Ah = (const __nv_bfloat16*)g_ah4;
    const __nv_bfloat16* Al = (const __nv_bfloat16*)g_al4;
    const __nv_bfloat16* Wh = (const __nv_bfloat16*)g_wh4 + (size_t)wbase + (size_t)wsel * K * Nt;
    const __nv_bfloat16* Wl = (const __nv_bfloat16*)g_wl4 + (size_t)wbase + (size_t)wsel * K * Nt;

    const float* bias;
    int csel;
    switch (wsel) {
        case 0: bias = b0; csel = c0; break;
        case 1: bias = b1; csel = c1; break;
        case 2: bias = b2; csel = c2; break;
        default: bias = b3; csel = c3; break;
    }
    float* C = sel(csel);

    float acc[4][4][4];
#pragma unroll
    for (int i = 0; i < 4; i++)
#pragma unroll
        for (int j = 0; j < 4; j++)
#pragma unroll
            for (int q = 0; q < 4; q++) acc[i][j][q] = 0.f;

    const int l_row = tid >> 2;
    const int l_kq = tid & 3;
    const int nChunks = K >> 5;

    const int grow0 = rowBase + l_row;
    const int grow1 = rowBase + l_row + 64;
    const int a_ok0 = (grow0 < M) ? 16 : 0;
    const int a_ok1 = (grow1 < M) ? 16 : 0;
    const int n0 = colBase + l_row;
    const int n1 = colBase + l_row + 64;
    const uint32_t soff0 = (uint32_t)(l_row * 80 + l_kq * 16);
    const uint32_t soff1 = soff0 + 64 * 80;

    auto issue = [&](int c, int b) {
        const int k0 = c << 5;
        uint32_t bb = sbase + b * BUF_SZ;
        cp16(bb + OFF_AH + soff0, Ah + (size_t)grow0 * K + k0 + l_kq * 8, a_ok0);
        cp16(bb + OFF_AL + soff0, Al + (size_t)grow0 * K + k0 + l_kq * 8, a_ok0);
        cp16(bb + OFF_AH + soff1, Ah + (size_t)grow1 * K + k0 + l_kq * 8, a_ok1);
        cp16(bb + OFF_AL + soff1, Al + (size_t)grow1 * K + k0 + l_kq * 8, a_ok1);
        cp16(bb + OFF_BH + soff0, Wh + (size_t)n0 * K + k0 + l_kq * 8, 16);
        cp16(bb + OFF_BL + soff0, Wl + (size_t)n0 * K + k0 + l_kq * 8, 16);
        cp16(bb + OFF_BH + soff1, Wh + (size_t)n1 * K + k0 + l_kq * 8, 16);
        cp16(bb + OFF_BL + soff1, Wl + (size_t)n1 * K + k0 + l_kq * 8, 16);
        cp_commit();
    };

    issue(0, 0);

    int buf = 0;
    for (int c = 0; c < nChunks; c++) {
        if (c + 1 < nChunks) {
            issue(c + 1, buf ^ 1);
            cp_wait1();
        } else {
            cp_wait0();
        }
        __syncthreads();

        uint32_t bb = sbase + buf * BUF_SZ;
        const int lr = lid & 15;
        const int lc = lid >> 4;
        uint32_t AHB = bb + OFF_AH, ALB = bb + OFF_AL;
        uint32_t BHB = bb + OFF_BH, BLB = bb + OFF_BL;
#pragma unroll
        for (int ks = 0; ks < 2; ks++) {
            uint32_t koff = (uint32_t)(ks * 32 + lc * 16);
            uint32_t ah[4][4], al[4][4], bh[4][2], bl[4][2];
#pragma unroll
            for (int i = 0; i < 4; i++) {
                uint32_t ro = (uint32_t)((wm * 64 + i * 16 + lr) * 80) + koff;
                ldm_x4(ah[i][0], ah[i][1], ah[i][2], ah[i][3], AHB + ro);
                ldm_x4(al[i][0], al[i][1], al[i][2], al[i][3], ALB + ro);
            }
#pragma unroll
            for (int j2 = 0; j2 < 2; j2++) {
                uint32_t ro = (uint32_t)((wn * 32 + j2 * 16 + lr) * 80) + koff;
                uint32_t r0, r1, r2, r3;
                ldm_x4(r0, r1, r2, r3, BHB + ro);
                bh[j2 * 2 + 0][0] = r0; bh[j2 * 2 + 0][1] = r2;
                bh[j2 * 2 + 1][0] = r1; bh[j2 * 2 + 1][1] = r3;
                ldm_x4(r0, r1, r2, r3, BLB + ro);
                bl[j2 * 2 + 0][0] = r0; bl[j2 * 2 + 0][1] = r2;
                bl[j2 * 2 + 1][0] = r1; bl[j2 * 2 + 1][1] = r3;
            }
#pragma unroll
            for (int i = 0; i < 4; i++)
#pragma unroll
                for (int j = 0; j < 4; j++) {
                    mma_bf16(acc[i][j], ah[i], bh[j]);
                    mma_bf16(acc[i][j], ah[i], bl[j]);
                    mma_bf16(acc[i][j], al[i], bh[j]);
                }
        }
        __syncthreads();
        buf ^= 1;
    }

    const int lr4 = lid >> 2;
    const int lc2 = (lid & 3) * 2;
#pragma unroll
    for (int j = 0; j < 4; j++) {
        int gc = colBase + wn * 32 + j * 8 + lc2;
        float bi0 = bias[gc], bi1 = bias[gc + 1];
#pragma unroll
        for (int i = 0; i < 4; i++) {
            int gr0 = rowBase + wm * 64 + i * 16 + lr4;
            int gr1 = gr0 + 8;
            if (gr0 < M) {
                float2 o = make_float2(acc[i][j][0] + bi0, acc[i][j][1] + bi1);
                *(float2*)(C + (size_t)gr0 * Nt + gc) = o;
            }
            if (gr1 < M) {
                float2 o = make_float2(acc[i][j][2] + bi0, acc[i][j][3] + bi1);
                *(float2*)(C + (size_t)gr1 * Nt + gc) = o;
            }
        }
    }
}

// ================= fused per-node edge kernel (two-pass) + optional pooling =================
// do_split: emit bf16 hi/lo of final h (layer 1). do_pool: block-reduce pooling (layer 2, d=128).
__global__ __launch_bounds__(256)
void edge_fused_kernel(int Nn, int d, int h_sel, float inv_sqrt_d,
                       int do_split, int do_pool) {
    __shared__ float sc[8][DEG_CAP];
    __shared__ float ps[128];
    __shared__ unsigned pm[128];
    int gw = (blockIdx.x * blockDim.x + threadIdx.x) >> 5;
    int lane = threadIdx.x & 31;
    int wIn = threadIdx.x >> 5;

    if (do_pool && threadIdx.x < 128) {
        ps[threadIdx.x] = 0.f;
        pm[threadIdx.x] = ENC_NEG_INF;
    }

    const int nv = d >> 7;
    float4 h0 = make_float4(0.f, 0.f, 0.f, 0.f);
    bool valid = (gw < Nn);

    if (valid) {
        int beg = g_off[gw];
        int deg = g_off[gw + 1] - beg;

        float4 a0 = make_float4(0.f, 0.f, 0.f, 0.f);
        float4 a1 = make_float4(0.f, 0.f, 0.f, 0.f);

        if (deg > 0) {
            const float* qr = g_q + (size_t)gw * d;
            float4 q0 = *(const float4*)(qr + lane * 4);
            float4 q1 = make_float4(0.f, 0.f, 0.f, 0.f);
            if (nv > 1) q1 = *(const float4*)(qr + 128 + lane * 4);

            // ---- pass 1: scores + max (2-edge pipelined) ----
            float mx = -FLT_MAX;
            int j = 0;
            for (; j + 1 < deg; j += 2) {
                int s0 = g_ssrc[beg + j];
                int s1 = g_ssrc[beg + j + 1];
                const float* k0p = g_k + (size_t)s0 * d;
                const float* k1p = g_k + (size_t)s1 * d;
                float4 b0 = *(const float4*)(k0p + lane * 4);
                float4 c0 = *(const float4*)(k1p + lane * 4);
                float sa = q0.x * b0.x + q0.y * b0.y + q0.z * b0.z + q0.w * b0.w;
                float sb = q0.x * c0.x + q0.y * c0.y + q0.z * c0.z + q0.w * c0.w;
                if (nv > 1) {
                    float4 b1 = *(const float4*)(k0p + 128 + lane * 4);
                    float4 c1 = *(const float4*)(k1p + 128 + lane * 4);
                    sa += q1.x * b1.x + q1.y * b1.y + q1.z * b1.z + q1.w * b1.w;
                    sb += q1.x * c1.x + q1.y * c1.y + q1.z * c1.z + q1.w * c1.w;
                }
#pragma unroll
                for (int o = 16; o; o >>= 1) {
                    sa += __shfl_xor_sync(0xFFFFFFFFu, sa, o);
                    sb += __shfl_xor_sync(0xFFFFFFFFu, sb, o);
                }
                sa *= inv_sqrt_d;
                sb *= inv_sqrt_d;
                mx = fmaxf(mx, fmaxf(sa, sb));
                if (lane == 0) {
                    if (j < DEG_CAP) sc[wIn][j] = sa; else g_score[beg + j] = sa;
                    if (j + 1 < DEG_CAP) sc[wIn][j + 1] = sb; else g_score[beg + j + 1] = sb;
                }
            }
            if (j < deg) {
                int s = g_ssrc[beg + j];
                const float* kr = g_k + (size_t)s * d;
                float4 b0 = *(const float4*)(kr + lane * 4);
                float sum = q0.x * b0.x + q0.y * b0.y + q0.z * b0.z + q0.w * b0.w;
                if (nv > 1) {
                    float4 b1 = *(const float4*)(kr + 128 + lane * 4);
                    sum += q1.x * b1.x + q1.y * b1.y + q1.z * b1.z + q1.w * b1.w;
                }
#pragma unroll
                for (int o = 16; o; o >>= 1) sum += __shfl_xor_sync(0xFFFFFFFFu, sum, o);
                sum *= inv_sqrt_d;
                mx = fmaxf(mx, sum);
                if (lane == 0) {
                    if (j < DEG_CAP) sc[wIn][j] = sum; else g_score[beg + j] = sum;
                }
            }
            __syncwarp();

            // ---- pass 2: exp + denom ----
            float den = 0.f;
            for (int jj = lane; jj < deg; jj += 32) {
                float v = (jj < DEG_CAP) ? sc[wIn][jj] : g_score[beg + jj];
                float e = __expf(v - mx);
                if (jj < DEG_CAP) sc[wIn][jj] = e;
                else g_score[beg + jj] = e;
                den += e;
            }
#pragma unroll
            for (int o = 16; o; o >>= 1) den += __shfl_xor_sync(0xFFFFFFFFu, den, o);
            float rden = 1.f / den;
            __syncwarp();

            // ---- pass 3: weighted aggregate (4-edge unrolled) ----
            j = 0;
            for (; j + 3 < deg; j += 4) {
                int s0 = g_ssrc[beg + j];
                int s1 = g_ssrc[beg + j + 1];
                int s2 = g_ssrc[beg + j + 2];
                int s3 = g_ssrc[beg + j + 3];
                float e0 = (j < DEG_CAP) ? sc[wIn][j] : g_score[beg + j];
                float e1 = (j + 1 < DEG_CAP) ? sc[wIn][j + 1] : g_score[beg + j + 1];
                float e2 = (j + 2 < DEG_CAP) ? sc[wIn][j + 2] : g_score[beg + j + 2];
                float e3 = (j + 3 < DEG_CAP) ? sc[wIn][j + 3] : g_score[beg + j + 3];
                float al0 = e0 * rden, al1 = e1 * rden, al2 = e2 * rden, al3 = e3 * rden;
                const float* v0p = g_v + (size_t)s0 * d;
                const float* v1p = g_v + (size_t)s1 * d;
                const float* v2p = g_v + (size_t)s2 * d;
                const float* v3p = g_v + (size_t)s3 * d;
                float4 b0 = *(const float4*)(v0p + lane * 4);
                float4 c0 = *(const float4*)(v1p + lane * 4);
                float4 d0 = *(const float4*)(v2p + lane * 4);
                float4 f0 = *(const float4*)(v3p + lane * 4);
                a0.x += al0 * b0.x + al1 * c0.x + al2 * d0.x + al3 * f0.x;
                a0.y += al0 * b0.y + al1 * c0.y + al2 * d0.y + al3 * f0.y;
                a0.z += al0 * b0.z + al1 * c0.z + al2 * d0.z + al3 * f0.z;
                a0.w += al0 * b0.w + al1 * c0.w + al2 * d0.w + al3 * f0.w;
                if (nv > 1) {
                    float4 b1 = *(const float4*)(v0p + 128 + lane * 4);
                    float4 c1 = *(const float4*)(v1p + 128 + lane * 4);
                    float4 d1 = *(const float4*)(v2p + 128 + lane * 4);
                    float4 f1 = *(const float4*)(v3p + 128 + lane * 4);
                    a1.x += al0 * b1.x + al1 * c1.x + al2 * d1.x + al3 * f1.x;
                    a1.y += al0 * b1.y + al1 * c1.y + al2 * d1.y + al3 * f1.y;
                    a1.z += al0 * b1.z + al1 * c1.z + al2 * d1.z + al3 * f1.z;
                    a1.w += al0 * b1.w + al1 * c1.w + al2 * d1.w + al3 * f1.w;
                }
            }
            for (; j < deg; j++) {
                int s = g_ssrc[beg + j];
                float e = (j < DEG_CAP) ? sc[wIn][j] : g_score[beg + j];
                float alpha = e * rden;
                const float* vr = g_v + (size_t)s * d;
                float4 b0 = *(const float4*)(vr + lane * 4);
                a0.x += alpha * b0.x; a0.y += alpha * b0.y;
                a0.z += alpha * b0.z; a0.w += alpha * b0.w;
                if (nv > 1) {
                    float4 b1 = *(const float4*)(vr + 128 + lane * 4);
                    a1.x += alpha * b1.x; a1.y += alpha * b1.y;
                    a1.z += alpha * b1.z; a1.w += alpha * b1.w;
                }
            }
        }

        float* hr = sel(h_sel) + (size_t)gw * d;
        h0 = *(float4*)(hr + lane * 4);
        h0.x += a0.x; h0.y += a0.y; h0.z += a0.z; h0.w += a0.w;
        *(float4*)(hr + lane * 4) = h0;
        float4 h1 = make_float4(0.f, 0.f, 0.f, 0.f);
        if (nv > 1) {
            h1 = *(float4*)(hr + 128 + lane * 4);
            h1.x += a1.x; h1.y += a1.y; h1.z += a1.z; h1.w += a1.w;
            *(float4*)(hr + 128 + lane * 4) = h1;
        }

        if (do_split) {
            __nv_bfloat16* AhP = (__nv_bfloat16*)g_ah4;
            __nv_bfloat16* AlP = (__nv_bfloat16*)g_al4;
            float lx, ly, lz, lw;
            float hx = bf_hi_val(h0.x, lx);
            float hy = bf_hi_val(h0.y, ly);
            float hz = bf_hi_val(h0.z, lz);
            float hw = bf_hi_val(h0.w, lw);
            *(uint2*)(AhP + (size_t)gw * d + lane * 4) = make_uint2(pack_bf(hx, hy), pack_bf(hz, hw));
            *(uint2*)(AlP + (size_t)gw * d + lane * 4) = make_uint2(pack_bf(lx, ly), pack_bf(lz, lw));
            if (nv > 1) {
                float hx1 = bf_hi_val(h1.x, lx);
                float hy1 = bf_hi_val(h1.y, ly);
                float hz1 = bf_hi_val(h1.z, lz);
                float hw1 = bf_hi_val(h1.w, lw);
                *(uint2*)(AhP + (size_t)gw * d + 128 + lane * 4) = make_uint2(pack_bf(hx1, hy1), pack_bf(hz1, hw1));
                *(uint2*)(AlP + (size_t)gw * d + 128 + lane * 4) = make_uint2(pack_bf(lx, ly), pack_bf(lz, lw));
            }
        }
    }

    // ---- fused pooling (layer 2, d=128) ----
    if (do_pool) {
        __syncthreads();
        if (valid) {
            int c = lane * 4;
            atomicAdd(&ps[c + 0], h0.x);
            atomicAdd(&ps[c + 1], h0.y);
            atomicAdd(&ps[c + 2], h0.z);
            atomicAdd(&ps[c + 3], h0.w);
            atomicMax(&pm[c + 0], fenc(h0.x));
            atomicMax(&pm[c + 1], fenc(h0.y));
            atomicMax(&pm[c + 2], fenc(h0.z));
            atomicMax(&pm[c + 3], fenc(h0.w));
        }
        __syncthreads();
        if (threadIdx.x < 128) {
            atomicAdd(&g_psum[threadIdx.x], ps[threadIdx.x]);
            atomicMax(&g_pmax[threadIdx.x], pm[threadIdx.x]);
        }
    }
}

// ---------------- final pooling output ----------------
__global__ void pool_final_kernel(float* __restrict__ out, int M, int d) {
    int c = threadIdx.x;
    if (c < d) {
        out[c] = g_psum[c] / (float)M;
        out[d + c] = fdec(g_pmax[c]);
    }
}

// ---------------- launch ----------------
extern "C" void kernel_launch(void* const* d_in, const int* in_sizes, int n_in,
                              void* d_out, int out_size) {
    const float* x   = (const float*)d_in[0];
    const void*  ei  = d_in[1];
    const float* Wq1 = (const float*)d_in[3];
    const float* bq1 = (const float*)d_in[4];
    const float* Wk1 = (const float*)d_in[5];
    const float* bk1 = (const float*)d_in[6];
    const float* Wv1 = (const float*)d_in[7];
    const float* bv1 = (const float*)d_in[8];
    const float* Ws1 = (const float*)d_in[9];
    const float* bs1 = (const float*)d_in[10];
    const float* Wq2 = (const float*)d_in[11];
    const float* bq2 = (const float*)d_in[12];
    const float* Wk2 = (const float*)d_in[13];
    const float* bk2 = (const float*)d_in[14];
    const float* Wv2 = (const float*)d_in[15];
    const float* bv2 = (const float*)d_in[16];
    const float* Ws2 = (const float*)d_in[17];
    const float* bs2 = (const float*)d_in[18];
    float* out = (float*)d_out;

    const int D_IN = 512, D_HID = 256, D_OUT = 128;
    int Nn = in_sizes[0] / D_IN;
    int E  = in_sizes[2];

    static cudaStream_t s2 = nullptr;
    static cudaEvent_t evFork = nullptr, evJoin = nullptr;
    if (!s2) {
        cudaFuncSetAttribute(gemm_mma_kernel,
                             cudaFuncAttributeMaxDynamicSharedMemorySize, GEMM_SMEM);
        cudaStreamCreateWithFlags(&s2, cudaStreamNonBlocking);
        cudaEventCreateWithFlags(&evFork, cudaEventDisableTiming);
        cudaEventCreateWithFlags(&evJoin, cudaEventDisableTiming);
    }

    int nb = (Nn + 255) / 256;
    int t4 = Nn * D_IN / 4;

    // ---- fork: entire graph-prep chain on side stream ----
    cudaEventRecord(evFork, 0);
    cudaStreamWaitEvent(s2, evFork, 0);
    detect_zero_kernel<<<nb, 256, 0, s2>>>((const unsigned*)ei, E, Nn);
    convert_kernel<<<(E + 255) / 256, 256, 0, s2>>>(ei, E);
    part_sum_kernel<<<nb, 256, 0, s2>>>(Nn);
    part_scan_kernel<<<1, 256, 0, s2>>>(nb, Nn);
    off_kernel<<<nb, 256, 0, s2>>>(Nn);
    permute_kernel<<<(E + 255) / 256, 256, 0, s2>>>(E);
    cudaEventRecord(evJoin, s2);

    // ---- main stream: splits -> layer-1 GEMM (concurrent with graph prep) ----
    {
        int bA = (t4 + 255) / 256;
        int bW1 = (4 * D_IN * D_HID) / 256;
        int bW2 = (4 * D_HID * D_OUT) / 256;
        int b1 = bA, b2 = b1 + bW1, b3 = b2 + bW2;
        fused_split_kernel<<<b3, 256>>>(x, t4,
                                        Wq1, Wk1, Wv1, Ws1, Wq2, Wk2, Wv2, Ws2,
                                        b1, b2, b3);
    }

    int nTiles = (Nn + 127) / 128;
    int edgeBlks = (Nn * 32 + 255) / 256;

    {
        dim3 g(8, nTiles);
        gemm_mma_kernel<<<g, 256, GEMM_SMEM>>>(
            0, bq1, bk1, bv1, bs1, 0, 1, 2, 3, Nn, D_IN, D_HID);
    }

    // join graph prep before edge phase
    cudaStreamWaitEvent(0, evJoin, 0);
    edge_fused_kernel<<<edgeBlks, 256>>>(Nn, D_HID, 3,
        (float)(1.0 / sqrt((double)D_HID)), 1, 0);

    // ===== layer 2 =====
    {
        dim3 g(4, nTiles);
        gemm_mma_kernel<<<g, 256, GEMM_SMEM>>>(
            WOFF_L2, bq2, bk2, bv2, bs2, 0, 1, 2, 4, Nn, D_HID, D_OUT);
    }
    // edge + fused pooling
    edge_fused_kernel<<<edgeBlks, 256>>>(Nn, D_OUT, 4,
        (float)(1.0 / sqrt((double)D_OUT)), 0, 1);

    pool_final_kernel<<<1, 256>>>(out, Nn, D_OUT);
}